// round 1
// baseline (speedup 1.0000x reference)
#include <cuda_runtime.h>
#include <cstdint>

#define EMBED   2048
#define NHEADS  16
#define HDIM    128
#define SEQ     2048
#define BATCH   2
#define QKVN    (3*EMBED)      /* 6144 */
#define MROWS   (BATCH*SEQ)    /* 4096 */

// Scratch buffers (static device globals — allocation-free).
__device__ float g_qkv[(size_t)MROWS * QKVN];   // [b*s, 6144]  (Q|K|V per row)
__device__ float g_attn[(size_t)MROWS * EMBED]; // attention output, [b*s, 2048]

// ---------------------------------------------------------------------------
// SGEMM with bias: C[M,N] = A[M,K] * B[K,N] + bias[N]
// 128x128 block tile, BK=16, 256 threads, 8x8 per-thread microtile.
// ---------------------------------------------------------------------------
__global__ __launch_bounds__(256, 2)
void sgemm_bias(const float* __restrict__ A, const float* __restrict__ B,
                const float* __restrict__ bias, float* __restrict__ C,
                int M, int N, int K)
{
    __shared__ float As[16][128];   // A tile transposed: As[k][m]
    __shared__ float Bs[16][128];

    const int tid = threadIdx.x;
    const int tx  = tid & 15;
    const int ty  = tid >> 4;
    const int bx  = blockIdx.x;
    const int by  = blockIdx.y;

    const float* Ab = A + (size_t)by * 128 * K;
    const float* Bb = B + (size_t)bx * 128;

    float acc[2][2][4][4];
    #pragma unroll
    for (int ga = 0; ga < 2; ga++)
        #pragma unroll
        for (int gb = 0; gb < 2; gb++)
            #pragma unroll
            for (int i = 0; i < 4; i++)
                #pragma unroll
                for (int j = 0; j < 4; j++)
                    acc[ga][gb][i][j] = 0.f;

    for (int k0 = 0; k0 < K; k0 += 16) {
        // Load A tile 128x16 (coalesced float4), store transposed.
        #pragma unroll
        for (int t = 0; t < 2; t++) {
            int idx = tid + t * 256;
            int row = idx >> 2;          // 0..127
            int kc  = (idx & 3) << 2;    // 0,4,8,12
            float4 a = *(const float4*)(Ab + (size_t)row * K + k0 + kc);
            As[kc + 0][row] = a.x;
            As[kc + 1][row] = a.y;
            As[kc + 2][row] = a.z;
            As[kc + 3][row] = a.w;
        }
        // Load B tile 16x128 (coalesced float4).
        #pragma unroll
        for (int t = 0; t < 2; t++) {
            int idx = tid + t * 256;
            int row = idx >> 5;          // 0..15
            int c4  = (idx & 31) << 2;
            *(float4*)(&Bs[row][c4]) =
                *(const float4*)(Bb + (size_t)(k0 + row) * N + c4);
        }
        __syncthreads();

        #pragma unroll
        for (int k = 0; k < 16; k++) {
            float4 a0 = *(const float4*)(&As[k][4 * ty]);
            float4 a1 = *(const float4*)(&As[k][4 * ty + 64]);
            float4 b0 = *(const float4*)(&Bs[k][4 * tx]);        // conflict-free starts
            float4 b1 = *(const float4*)(&Bs[k][4 * tx + 64]);
            float av[2][4] = {{a0.x, a0.y, a0.z, a0.w}, {a1.x, a1.y, a1.z, a1.w}};
            float bv[2][4] = {{b0.x, b0.y, b0.z, b0.w}, {b1.x, b1.y, b1.z, b1.w}};
            #pragma unroll
            for (int ga = 0; ga < 2; ga++)
                #pragma unroll
                for (int i = 0; i < 4; i++)
                    #pragma unroll
                    for (int gb = 0; gb < 2; gb++)
                        #pragma unroll
                        for (int j = 0; j < 4; j++)
                            acc[ga][gb][i][j] += av[ga][i] * bv[gb][j];
        }
        __syncthreads();
    }

    // Epilogue: add bias, float4 stores.
    #pragma unroll
    for (int ga = 0; ga < 2; ga++)
        #pragma unroll
        for (int i = 0; i < 4; i++) {
            int row = by * 128 + 4 * ty + 64 * ga + i;
            #pragma unroll
            for (int gb = 0; gb < 2; gb++) {
                int col = bx * 128 + 4 * tx + 64 * gb;
                float4 bb = *(const float4*)(bias + col);
                float4 o;
                o.x = acc[ga][gb][i][0] + bb.x;
                o.y = acc[ga][gb][i][1] + bb.y;
                o.z = acc[ga][gb][i][2] + bb.z;
                o.w = acc[ga][gb][i][3] + bb.w;
                *(float4*)(C + (size_t)row * N + col) = o;
            }
        }
}

// ---------------------------------------------------------------------------
// Flash-attention (fp32, causal). BM=128 queries x BN=64 keys per iteration.
// 256 threads: ty=tid/16 owns 8 query rows (8*ty+r); tx=tid%15... tx=tid&15
// owns cols {tx+16c} of S and cols {4tx..4tx+3, 64+4tx..} of O/V.
// ---------------------------------------------------------------------------
#define KPAD 132
#define ATTN_SMEM ((128*128 + 64*KPAD + 64*128 + 128*64) * 4)

__global__ __launch_bounds__(256, 1)
void attn_kernel()
{
    extern __shared__ float sm[];
    float* Qs = sm;                 // 128 x 128 (pre-scaled Q)
    float* Ks = Qs + 128 * 128;     // 64 x 132 (padded: conflict-free f4 reads)
    float* Vs = Ks + 64 * KPAD;     // 64 x 128
    float* Ss = Vs + 64 * 128;      // 128 x 64 (P tile)

    const int tid = threadIdx.x;
    const int tx  = tid & 15;
    const int ty  = tid >> 4;
    const int qt  = (int)gridDim.x - 1 - (int)blockIdx.x;  // big tiles first
    const int bh  = blockIdx.y;
    const int b   = bh >> 4;
    const int h   = bh & 15;
    const float scale = 0.08838834764831845f;  // 1/sqrt(128)

    const size_t rowbase = (size_t)b * SEQ;

    // Load + pre-scale Q tile (128 x 128).
    #pragma unroll
    for (int t = 0; t < 16; t++) {
        int idx = tid + t * 256;
        int r   = idx >> 5;
        int c4  = (idx & 31) << 2;
        const float* src = g_qkv + (rowbase + qt * 128 + r) * QKVN + h * HDIM + c4;
        float4 v = *(const float4*)src;
        v.x *= scale; v.y *= scale; v.z *= scale; v.w *= scale;
        *(float4*)(Qs + r * 128 + c4) = v;
    }

    float m[8], l[8], O[8][8];
    #pragma unroll
    for (int r = 0; r < 8; r++) {
        m[r] = -1e30f; l[r] = 0.f;
        #pragma unroll
        for (int c = 0; c < 8; c++) O[r][c] = 0.f;
    }

    const int nkt = 2 * qt + 2;      // kv tiles covering keys <= qt*128+127
    for (int kt = 0; kt < nkt; kt++) {
        __syncthreads();  // previous PV done before overwriting K/V/S
        // Load K, V tiles (64 x 128 each).
        #pragma unroll
        for (int t = 0; t < 8; t++) {
            int idx = tid + t * 256;
            int r   = idx >> 5;
            int c4  = (idx & 31) << 2;
            const float* src = g_qkv + (rowbase + kt * 64 + r) * QKVN + h * HDIM + c4;
            *(float4*)(Ks + r * KPAD + c4) = *(const float4*)(src + EMBED);
            *(float4*)(Vs + r * 128 + c4)  = *(const float4*)(src + 2 * EMBED);
        }
        __syncthreads();

        // S = Q K^T (Q pre-scaled). 8 rows x 4 cols per thread.
        float s[8][4];
        #pragma unroll
        for (int r = 0; r < 8; r++)
            #pragma unroll
            for (int c = 0; c < 4; c++) s[r][c] = 0.f;

        #pragma unroll
        for (int d4 = 0; d4 < 32; d4++) {
            float4 k4[4];
            #pragma unroll
            for (int c = 0; c < 4; c++)
                k4[c] = *(const float4*)(Ks + (tx + 16 * c) * KPAD + 4 * d4);
            #pragma unroll
            for (int r = 0; r < 8; r++) {
                float4 q4 = *(const float4*)(Qs + (8 * ty + r) * 128 + 4 * d4);
                #pragma unroll
                for (int c = 0; c < 4; c++) {
                    s[r][c] += q4.x * k4[c].x;
                    s[r][c] += q4.y * k4[c].y;
                    s[r][c] += q4.z * k4[c].z;
                    s[r][c] += q4.w * k4[c].w;
                }
            }
        }

        // Causal mask (only the last two kv tiles straddle the diagonal).
        if (kt >= 2 * qt) {
            #pragma unroll
            for (int r = 0; r < 8; r++) {
                int qi = qt * 128 + 8 * ty + r;
                #pragma unroll
                for (int c = 0; c < 4; c++) {
                    int kj = kt * 64 + tx + 16 * c;
                    if (kj > qi) s[r][c] = -1e30f;
                }
            }
        }

        // Online softmax (row reductions over the 16 tx lanes).
        #pragma unroll
        for (int r = 0; r < 8; r++) {
            float mx = fmaxf(fmaxf(s[r][0], s[r][1]), fmaxf(s[r][2], s[r][3]));
            #pragma unroll
            for (int off = 8; off > 0; off >>= 1)
                mx = fmaxf(mx, __shfl_xor_sync(0xffffffffu, mx, off));
            float mnew = fmaxf(m[r], mx);
            float corr = __expf(m[r] - mnew);
            m[r] = mnew;
            float rs = 0.f;
            #pragma unroll
            for (int c = 0; c < 4; c++) {
                float p = __expf(s[r][c] - mnew);
                Ss[(8 * ty + r) * 64 + tx + 16 * c] = p;
                rs += p;
            }
            #pragma unroll
            for (int off = 8; off > 0; off >>= 1)
                rs += __shfl_xor_sync(0xffffffffu, rs, off);
            l[r] = l[r] * corr + rs;
            #pragma unroll
            for (int c = 0; c < 8; c++) O[r][c] *= corr;
        }
        __syncthreads();  // P visible before PV

        // O += P @ V
        #pragma unroll 4
        for (int j = 0; j < 64; j++) {
            float4 v0 = *(const float4*)(Vs + j * 128 + 4 * tx);
            float4 v1 = *(const float4*)(Vs + j * 128 + 64 + 4 * tx);
            #pragma unroll
            for (int r = 0; r < 8; r++) {
                float p = Ss[(8 * ty + r) * 64 + j];
                O[r][0] += p * v0.x; O[r][1] += p * v0.y;
                O[r][2] += p * v0.z; O[r][3] += p * v0.w;
                O[r][4] += p * v1.x; O[r][5] += p * v1.y;
                O[r][6] += p * v1.z; O[r][7] += p * v1.w;
            }
        }
    }

    // Normalize and write attention output.
    #pragma unroll
    for (int r = 0; r < 8; r++) {
        float inv = 1.0f / l[r];
        int srow = qt * 128 + 8 * ty + r;
        float* dst = g_attn + (rowbase + srow) * EMBED + h * HDIM + 4 * tx;
        float4 o0, o1;
        o0.x = O[r][0] * inv; o0.y = O[r][1] * inv;
        o0.z = O[r][2] * inv; o0.w = O[r][3] * inv;
        o1.x = O[r][4] * inv; o1.y = O[r][5] * inv;
        o1.z = O[r][6] * inv; o1.w = O[r][7] * inv;
        *(float4*)dst        = o0;
        *(float4*)(dst + 64) = o1;
    }
}

// ---------------------------------------------------------------------------
extern "C" void kernel_launch(void* const* d_in, const int* in_sizes, int n_in,
                              void* d_out, int out_size)
{
    const float* x    = (const float*)d_in[0];
    const float* Wqkv = (const float*)d_in[1];
    const float* bqkv = (const float*)d_in[2];
    const float* Wout = (const float*)d_in[3];
    const float* bout = (const float*)d_in[4];
    float* out = (float*)d_out;

    float* qkvp = nullptr;
    float* attp = nullptr;
    cudaGetSymbolAddress((void**)&qkvp, g_qkv);
    cudaGetSymbolAddress((void**)&attp, g_attn);

    cudaFuncSetAttribute(attn_kernel,
                         cudaFuncAttributeMaxDynamicSharedMemorySize, ATTN_SMEM);

    // 1) QKV projection: [4096,2048] x [2048,6144] + b
    sgemm_bias<<<dim3(QKVN / 128, MROWS / 128), 256>>>(
        x, Wqkv, bqkv, qkvp, MROWS, QKVN, EMBED);

    // 2) Causal attention per (batch, head)
    attn_kernel<<<dim3(SEQ / 128, BATCH * NHEADS), 256, ATTN_SMEM>>>();

    // 3) Output projection: [4096,2048] x [2048,2048] + b
    sgemm_bias<<<dim3(EMBED / 128, MROWS / 128), 256>>>(
        attp, Wout, bout, out, MROWS, EMBED, EMBED);
}

// round 3
// speedup vs baseline: 1.6783x; 1.6783x over previous
#include <cuda_runtime.h>
#include <cstdint>

#define EMBED   2048
#define NHEADS  16
#define HDIM    128
#define SEQ     2048
#define BATCH   2
#define QKVN    (3*EMBED)      /* 6144 */
#define MROWS   (BATCH*SEQ)    /* 4096 */

// Scratch (static device globals — allocation-free).
__device__ float g_qkv[(size_t)MROWS * QKVN];    // QKV projection output (fp32)
__device__ float g_attn[(size_t)MROWS * EMBED];  // attention output (fp32)
__device__ float g_Bt[(size_t)QKVN * EMBED];     // transposed tf32 weights [N,K]

__device__ __forceinline__ float tf32r(float x) {
    uint32_t o;
    asm("cvt.rna.tf32.f32 %0, %1;" : "=r"(o) : "f"(x));
    return __uint_as_float(o);
}
__device__ __forceinline__ void mma_tf32(float* c,
                                         uint32_t a0, uint32_t a1, uint32_t a2, uint32_t a3,
                                         uint32_t b0, uint32_t b1) {
    asm volatile(
        "mma.sync.aligned.m16n8k8.row.col.f32.tf32.tf32.f32 "
        "{%0,%1,%2,%3}, {%4,%5,%6,%7}, {%8,%9}, {%0,%1,%2,%3};"
        : "+f"(c[0]), "+f"(c[1]), "+f"(c[2]), "+f"(c[3])
        : "r"(a0), "r"(a1), "r"(a2), "r"(a3), "r"(b0), "r"(b1));
}
#define FU(x) __float_as_uint(x)

// ---------------------------------------------------------------------------
// Weight transpose + tf32 round:  W[K,N] fp32  ->  Wt[N,K] tf32-in-fp32
// ---------------------------------------------------------------------------
__global__ void transpose_tf32(const float* __restrict__ W, float* __restrict__ Wt,
                               int K, int N)
{
    __shared__ float t[32][33];
    const int kb = blockIdx.y * 32, nb = blockIdx.x * 32;
    const int x = threadIdx.x, y = threadIdx.y;  // (32, 8)
    #pragma unroll
    for (int i = 0; i < 32; i += 8)
        t[y + i][x] = W[(size_t)(kb + y + i) * N + nb + x];
    __syncthreads();
    #pragma unroll
    for (int i = 0; i < 32; i += 8)
        Wt[(size_t)(nb + y + i) * K + kb + x] = tf32r(t[x][y + i]);
}

// ---------------------------------------------------------------------------
// TF32 mma.sync GEMM + bias: C[M,N] = A[M,K] * Bt[N,K]^T + bias[N]
// CTA 128x128, BK=32, 256 thr (8 warps, warp tile 32Mx64N), double-buffered.
// Smem k-columns permuted p(k) = (k%4)*8 + k/4 so each thread's tf32
// fragment elements are contiguous -> all fragment reads are LDS.128.
// ---------------------------------------------------------------------------
#define SST 36                      /* smem row stride (floats): conflict-free */
#define GEMM_SMEM (4 * 128 * SST * 4)

__global__ __launch_bounds__(256, 1)
void gemm_mma(const float* __restrict__ A, const float* __restrict__ Bt,
              const float* __restrict__ bias, float* __restrict__ C,
              int M, int N, int K)
{
    extern __shared__ float sm[];
    float* AsB = sm;                  // [2][128][SST]
    float* BsB = sm + 2 * 128 * SST;  // [2][128][SST]

    const int tid  = threadIdx.x;
    const int lane = tid & 31;
    const int wid  = tid >> 5;
    const int wm   = wid & 3;         // warp M tile (32 rows)
    const int wn   = wid >> 2;        // warp N tile (64 cols)
    const int m0   = blockIdx.y * 128;
    const int n0   = blockIdx.x * 128;
    const int gp   = lane >> 2;       // group id
    const int cc   = lane & 3;        // thread-in-group

    float4 pa[4], pb[4];

    auto ldg = [&](int k0) {
        #pragma unroll
        for (int t = 0; t < 4; t++) {
            int idx = tid + 256 * t;
            int row = idx >> 3, c4 = idx & 7;
            pa[t] = *(const float4*)(A  + (size_t)(m0 + row) * K + k0 + 4 * c4);
            pb[t] = *(const float4*)(Bt + (size_t)(n0 + row) * K + k0 + 4 * c4);
        }
    };
    auto sts = [&](int buf) {
        float* a = AsB + buf * 128 * SST;
        float* b = BsB + buf * 128 * SST;
        #pragma unroll
        for (int t = 0; t < 4; t++) {
            int idx = tid + 256 * t;
            int row = idx >> 3, c4 = idx & 7;
            float* ar = a + row * SST;
            float* br = b + row * SST;
            // original col = 4*c4 + i -> permuted slot 8*i + c4
            ar[c4]      = tf32r(pa[t].x);
            ar[8 + c4]  = tf32r(pa[t].y);
            ar[16 + c4] = tf32r(pa[t].z);
            ar[24 + c4] = tf32r(pa[t].w);
            br[c4]      = pb[t].x;       // Bt pre-rounded
            br[8 + c4]  = pb[t].y;
            br[16 + c4] = pb[t].z;
            br[24 + c4] = pb[t].w;
        }
    };

    float acc[2][8][4];
    #pragma unroll
    for (int ma = 0; ma < 2; ma++)
        #pragma unroll
        for (int nn = 0; nn < 8; nn++)
            #pragma unroll
            for (int q = 0; q < 4; q++) acc[ma][nn][q] = 0.f;

    ldg(0); sts(0); __syncthreads();

    const int NST = K >> 5;
    for (int s = 0; s < NST; s++) {
        const int buf = s & 1;
        if (s + 1 < NST) ldg((s + 1) << 5);

        const float* a = AsB + buf * 128 * SST;
        const float* b = BsB + buf * 128 * SST;

        #pragma unroll
        for (int h = 0; h < 2; h++) {          // half-stage: k-chunks 2h, 2h+1
            float4 av[4], bv[8];
            #pragma unroll
            for (int r = 0; r < 4; r++)
                av[r] = *(const float4*)(a + (wm * 32 + gp + 8 * r) * SST + 8 * cc + 4 * h);
            #pragma unroll
            for (int nn = 0; nn < 8; nn++)
                bv[nn] = *(const float4*)(b + (wn * 64 + gp + 8 * nn) * SST + 8 * cc + 4 * h);

            #pragma unroll
            for (int ma = 0; ma < 2; ma++) {
                // k-chunk 2h: components x (col cc), y (col cc+4)
                uint32_t a0 = FU(av[2 * ma].x), a1 = FU(av[2 * ma + 1].x);
                uint32_t a2 = FU(av[2 * ma].y), a3 = FU(av[2 * ma + 1].y);
                #pragma unroll
                for (int nn = 0; nn < 8; nn++)
                    mma_tf32(acc[ma][nn], a0, a1, a2, a3, FU(bv[nn].x), FU(bv[nn].y));
                // k-chunk 2h+1: components z, w
                uint32_t a4 = FU(av[2 * ma].z), a5 = FU(av[2 * ma + 1].z);
                uint32_t a6 = FU(av[2 * ma].w), a7 = FU(av[2 * ma + 1].w);
                #pragma unroll
                for (int nn = 0; nn < 8; nn++)
                    mma_tf32(acc[ma][nn], a4, a5, a6, a7, FU(bv[nn].z), FU(bv[nn].w));
            }
        }
        __syncthreads();
        if (s + 1 < NST) { sts(1 - buf); __syncthreads(); }
    }

    // Epilogue: bias add + float2 stores.
    #pragma unroll
    for (int ma = 0; ma < 2; ma++) {
        int rbase = m0 + wm * 32 + ma * 16 + gp;
        #pragma unroll
        for (int half = 0; half < 2; half++) {
            int r = rbase + 8 * half;
            #pragma unroll
            for (int nn = 0; nn < 8; nn++) {
                int col = n0 + wn * 64 + 8 * nn + 2 * cc;
                float2 bb = *(const float2*)(bias + col);
                float2 o;
                o.x = acc[ma][nn][2 * half + 0] + bb.x;
                o.y = acc[ma][nn][2 * half + 1] + bb.y;
                *(float2*)(C + (size_t)r * N + col) = o;
            }
        }
    }
}

// ---------------------------------------------------------------------------
// Flash-attention (fp32, causal) — unchanged passing Round-1 kernel.
// ---------------------------------------------------------------------------
#define KPAD 132
#define ATTN_SMEM ((128*128 + 64*KPAD + 64*128 + 128*64) * 4)

__global__ __launch_bounds__(256, 1)
void attn_kernel()
{
    extern __shared__ float sm[];
    float* Qs = sm;
    float* Ks = Qs + 128 * 128;
    float* Vs = Ks + 64 * KPAD;
    float* Ss = Vs + 64 * 128;

    const int tid = threadIdx.x;
    const int tx  = tid & 15;
    const int ty  = tid >> 4;
    const int qt  = (int)gridDim.x - 1 - (int)blockIdx.x;
    const int bh  = blockIdx.y;
    const int b   = bh >> 4;
    const int h   = bh & 15;
    const float scale = 0.08838834764831845f;

    const size_t rowbase = (size_t)b * SEQ;

    #pragma unroll
    for (int t = 0; t < 16; t++) {
        int idx = tid + t * 256;
        int r   = idx >> 5;
        int c4  = (idx & 31) << 2;
        const float* src = g_qkv + (rowbase + qt * 128 + r) * QKVN + h * HDIM + c4;
        float4 v = *(const float4*)src;
        v.x *= scale; v.y *= scale; v.z *= scale; v.w *= scale;
        *(float4*)(Qs + r * 128 + c4) = v;
    }

    float m[8], l[8], O[8][8];
    #pragma unroll
    for (int r = 0; r < 8; r++) {
        m[r] = -1e30f; l[r] = 0.f;
        #pragma unroll
        for (int c = 0; c < 8; c++) O[r][c] = 0.f;
    }

    const int nkt = 2 * qt + 2;
    for (int kt = 0; kt < nkt; kt++) {
        __syncthreads();
        #pragma unroll
        for (int t = 0; t < 8; t++) {
            int idx = tid + t * 256;
            int r   = idx >> 5;
            int c4  = (idx & 31) << 2;
            const float* src = g_qkv + (rowbase + kt * 64 + r) * QKVN + h * HDIM + c4;
            *(float4*)(Ks + r * KPAD + c4) = *(const float4*)(src + EMBED);
            *(float4*)(Vs + r * 128 + c4)  = *(const float4*)(src + 2 * EMBED);
        }
        __syncthreads();

        float s[8][4];
        #pragma unroll
        for (int r = 0; r < 8; r++)
            #pragma unroll
            for (int c = 0; c < 4; c++) s[r][c] = 0.f;

        #pragma unroll
        for (int d4 = 0; d4 < 32; d4++) {
            float4 k4[4];
            #pragma unroll
            for (int c = 0; c < 4; c++)
                k4[c] = *(const float4*)(Ks + (tx + 16 * c) * KPAD + 4 * d4);
            #pragma unroll
            for (int r = 0; r < 8; r++) {
                float4 q4 = *(const float4*)(Qs + (8 * ty + r) * 128 + 4 * d4);
                #pragma unroll
                for (int c = 0; c < 4; c++) {
                    s[r][c] += q4.x * k4[c].x;
                    s[r][c] += q4.y * k4[c].y;
                    s[r][c] += q4.z * k4[c].z;
                    s[r][c] += q4.w * k4[c].w;
                }
            }
        }

        if (kt >= 2 * qt) {
            #pragma unroll
            for (int r = 0; r < 8; r++) {
                int qi = qt * 128 + 8 * ty + r;
                #pragma unroll
                for (int c = 0; c < 4; c++) {
                    int kj = kt * 64 + tx + 16 * c;
                    if (kj > qi) s[r][c] = -1e30f;
                }
            }
        }

        #pragma unroll
        for (int r = 0; r < 8; r++) {
            float mx = fmaxf(fmaxf(s[r][0], s[r][1]), fmaxf(s[r][2], s[r][3]));
            #pragma unroll
            for (int off = 8; off > 0; off >>= 1)
                mx = fmaxf(mx, __shfl_xor_sync(0xffffffffu, mx, off));
            float mnew = fmaxf(m[r], mx);
            float corr = __expf(m[r] - mnew);
            m[r] = mnew;
            float rs = 0.f;
            #pragma unroll
            for (int c = 0; c < 4; c++) {
                float p = __expf(s[r][c] - mnew);
                Ss[(8 * ty + r) * 64 + tx + 16 * c] = p;
                rs += p;
            }
            #pragma unroll
            for (int off = 8; off > 0; off >>= 1)
                rs += __shfl_xor_sync(0xffffffffu, rs, off);
            l[r] = l[r] * corr + rs;
            #pragma unroll
            for (int c = 0; c < 8; c++) O[r][c] *= corr;
        }
        __syncthreads();

        #pragma unroll 4
        for (int j = 0; j < 64; j++) {
            float4 v0 = *(const float4*)(Vs + j * 128 + 4 * tx);
            float4 v1 = *(const float4*)(Vs + j * 128 + 64 + 4 * tx);
            #pragma unroll
            for (int r = 0; r < 8; r++) {
                float p = Ss[(8 * ty + r) * 64 + j];
                O[r][0] += p * v0.x; O[r][1] += p * v0.y;
                O[r][2] += p * v0.z; O[r][3] += p * v0.w;
                O[r][4] += p * v1.x; O[r][5] += p * v1.y;
                O[r][6] += p * v1.z; O[r][7] += p * v1.w;
            }
        }
    }

    #pragma unroll
    for (int r = 0; r < 8; r++) {
        float inv = 1.0f / l[r];
        int srow = qt * 128 + 8 * ty + r;
        float* dst = g_attn + (rowbase + srow) * EMBED + h * HDIM + 4 * tx;
        float4 o0, o1;
        o0.x = O[r][0] * inv; o0.y = O[r][1] * inv;
        o0.z = O[r][2] * inv; o0.w = O[r][3] * inv;
        o1.x = O[r][4] * inv; o1.y = O[r][5] * inv;
        o1.z = O[r][6] * inv; o1.w = O[r][7] * inv;
        *(float4*)dst        = o0;
        *(float4*)(dst + 64) = o1;
    }
}

// ---------------------------------------------------------------------------
extern "C" void kernel_launch(void* const* d_in, const int* in_sizes, int n_in,
                              void* d_out, int out_size)
{
    const float* x    = (const float*)d_in[0];
    const float* Wqkv = (const float*)d_in[1];
    const float* bqkv = (const float*)d_in[2];
    const float* Wout = (const float*)d_in[3];
    const float* bout = (const float*)d_in[4];
    float* out = (float*)d_out;

    float* qkvp = nullptr;
    float* attp = nullptr;
    float* btp  = nullptr;
    cudaGetSymbolAddress((void**)&qkvp, g_qkv);
    cudaGetSymbolAddress((void**)&attp, g_attn);
    cudaGetSymbolAddress((void**)&btp,  g_Bt);

    cudaFuncSetAttribute(attn_kernel,
                         cudaFuncAttributeMaxDynamicSharedMemorySize, ATTN_SMEM);
    cudaFuncSetAttribute(gemm_mma,
                         cudaFuncAttributeMaxDynamicSharedMemorySize, GEMM_SMEM);

    // 1) W_qkv -> [N,K] tf32
    transpose_tf32<<<dim3(QKVN / 32, EMBED / 32), dim3(32, 8)>>>(Wqkv, btp, EMBED, QKVN);
    // 2) QKV projection (tf32 mma.sync)
    gemm_mma<<<dim3(QKVN / 128, MROWS / 128), 256, GEMM_SMEM>>>(
        x, btp, bqkv, qkvp, MROWS, QKVN, EMBED);
    // 3) causal attention (fp32)
    attn_kernel<<<dim3(SEQ / 128, BATCH * NHEADS), 256, ATTN_SMEM>>>();
    // 4) W_out -> [N,K] tf32
    transpose_tf32<<<dim3(EMBED / 32, EMBED / 32), dim3(32, 8)>>>(Wout, btp, EMBED, EMBED);
    // 5) output projection (tf32 mma.sync)
    gemm_mma<<<dim3(EMBED / 128, MROWS / 128), 256, GEMM_SMEM>>>(
        attp, btp, bout, out, MROWS, EMBED, EMBED);
}

// round 4
// speedup vs baseline: 2.1752x; 1.2960x over previous
#include <cuda_runtime.h>
#include <cstdint>

#define EMBED   2048
#define NHEADS  16
#define HDIM    128
#define SEQ     2048
#define BATCH   2
#define QKVN    (3*EMBED)      /* 6144 */
#define MROWS   (BATCH*SEQ)    /* 4096 */

// Scratch (static device globals — allocation-free).
__device__ float g_qkv[(size_t)MROWS * QKVN];    // QKV projection output (fp32)
__device__ float g_attn[(size_t)MROWS * EMBED];  // attention output (fp32)
__device__ float g_Bt[(size_t)QKVN * EMBED];     // transposed tf32 weights [N,K]

__device__ __forceinline__ float tf32r(float x) {
    uint32_t o;
    asm("cvt.rna.tf32.f32 %0, %1;" : "=r"(o) : "f"(x));
    return __uint_as_float(o);
}
__device__ __forceinline__ void mma_tf32(float* c,
                                         uint32_t a0, uint32_t a1, uint32_t a2, uint32_t a3,
                                         uint32_t b0, uint32_t b1) {
    asm volatile(
        "mma.sync.aligned.m16n8k8.row.col.f32.tf32.tf32.f32 "
        "{%0,%1,%2,%3}, {%4,%5,%6,%7}, {%8,%9}, {%0,%1,%2,%3};"
        : "+f"(c[0]), "+f"(c[1]), "+f"(c[2]), "+f"(c[3])
        : "r"(a0), "r"(a1), "r"(a2), "r"(a3), "r"(b0), "r"(b1));
}
#define FU(x) __float_as_uint(x)

// ---------------------------------------------------------------------------
// Weight transpose + tf32 round:  W[K,N] fp32  ->  Wt[N,K] tf32-in-fp32
// ---------------------------------------------------------------------------
__global__ void transpose_tf32(const float* __restrict__ W, float* __restrict__ Wt,
                               int K, int N)
{
    __shared__ float t[32][33];
    const int kb = blockIdx.y * 32, nb = blockIdx.x * 32;
    const int x = threadIdx.x, y = threadIdx.y;  // (32, 8)
    #pragma unroll
    for (int i = 0; i < 32; i += 8)
        t[y + i][x] = W[(size_t)(kb + y + i) * N + nb + x];
    __syncthreads();
    #pragma unroll
    for (int i = 0; i < 32; i += 8)
        Wt[(size_t)(nb + y + i) * K + kb + x] = tf32r(t[x][y + i]);
}

// ---------------------------------------------------------------------------
// TF32 mma.sync GEMM + bias (unchanged passing Round-3 kernel).
// ---------------------------------------------------------------------------
#define SST 36
#define GEMM_SMEM (4 * 128 * SST * 4)

__global__ __launch_bounds__(256, 1)
void gemm_mma(const float* __restrict__ A, const float* __restrict__ Bt,
              const float* __restrict__ bias, float* __restrict__ C,
              int M, int N, int K)
{
    extern __shared__ float sm[];
    float* AsB = sm;
    float* BsB = sm + 2 * 128 * SST;

    const int tid  = threadIdx.x;
    const int lane = tid & 31;
    const int wid  = tid >> 5;
    const int wm   = wid & 3;
    const int wn   = wid >> 2;
    const int m0   = blockIdx.y * 128;
    const int n0   = blockIdx.x * 128;
    const int gp   = lane >> 2;
    const int cc   = lane & 3;

    float4 pa[4], pb[4];

    auto ldg = [&](int k0) {
        #pragma unroll
        for (int t = 0; t < 4; t++) {
            int idx = tid + 256 * t;
            int row = idx >> 3, c4 = idx & 7;
            pa[t] = *(const float4*)(A  + (size_t)(m0 + row) * K + k0 + 4 * c4);
            pb[t] = *(const float4*)(Bt + (size_t)(n0 + row) * K + k0 + 4 * c4);
        }
    };
    auto sts = [&](int buf) {
        float* a = AsB + buf * 128 * SST;
        float* b = BsB + buf * 128 * SST;
        #pragma unroll
        for (int t = 0; t < 4; t++) {
            int idx = tid + 256 * t;
            int row = idx >> 3, c4 = idx & 7;
            float* ar = a + row * SST;
            float* br = b + row * SST;
            ar[c4]      = tf32r(pa[t].x);
            ar[8 + c4]  = tf32r(pa[t].y);
            ar[16 + c4] = tf32r(pa[t].z);
            ar[24 + c4] = tf32r(pa[t].w);
            br[c4]      = pb[t].x;
            br[8 + c4]  = pb[t].y;
            br[16 + c4] = pb[t].z;
            br[24 + c4] = pb[t].w;
        }
    };

    float acc[2][8][4];
    #pragma unroll
    for (int ma = 0; ma < 2; ma++)
        #pragma unroll
        for (int nn = 0; nn < 8; nn++)
            #pragma unroll
            for (int q = 0; q < 4; q++) acc[ma][nn][q] = 0.f;

    ldg(0); sts(0); __syncthreads();

    const int NST = K >> 5;
    for (int s = 0; s < NST; s++) {
        const int buf = s & 1;
        if (s + 1 < NST) ldg((s + 1) << 5);

        const float* a = AsB + buf * 128 * SST;
        const float* b = BsB + buf * 128 * SST;

        #pragma unroll
        for (int h = 0; h < 2; h++) {
            float4 av[4], bv[8];
            #pragma unroll
            for (int r = 0; r < 4; r++)
                av[r] = *(const float4*)(a + (wm * 32 + gp + 8 * r) * SST + 8 * cc + 4 * h);
            #pragma unroll
            for (int nn = 0; nn < 8; nn++)
                bv[nn] = *(const float4*)(b + (wn * 64 + gp + 8 * nn) * SST + 8 * cc + 4 * h);

            #pragma unroll
            for (int ma = 0; ma < 2; ma++) {
                uint32_t a0 = FU(av[2 * ma].x), a1 = FU(av[2 * ma + 1].x);
                uint32_t a2 = FU(av[2 * ma].y), a3 = FU(av[2 * ma + 1].y);
                #pragma unroll
                for (int nn = 0; nn < 8; nn++)
                    mma_tf32(acc[ma][nn], a0, a1, a2, a3, FU(bv[nn].x), FU(bv[nn].y));
                uint32_t a4 = FU(av[2 * ma].z), a5 = FU(av[2 * ma + 1].z);
                uint32_t a6 = FU(av[2 * ma].w), a7 = FU(av[2 * ma + 1].w);
                #pragma unroll
                for (int nn = 0; nn < 8; nn++)
                    mma_tf32(acc[ma][nn], a4, a5, a6, a7, FU(bv[nn].z), FU(bv[nn].w));
            }
        }
        __syncthreads();
        if (s + 1 < NST) { sts(1 - buf); __syncthreads(); }
    }

    #pragma unroll
    for (int ma = 0; ma < 2; ma++) {
        int rbase = m0 + wm * 32 + ma * 16 + gp;
        #pragma unroll
        for (int half = 0; half < 2; half++) {
            int r = rbase + 8 * half;
            #pragma unroll
            for (int nn = 0; nn < 8; nn++) {
                int col = n0 + wn * 64 + 8 * nn + 2 * cc;
                float2 bb = *(const float2*)(bias + col);
                float2 o;
                o.x = acc[ma][nn][2 * half + 0] + bb.x;
                o.y = acc[ma][nn][2 * half + 1] + bb.y;
                *(float2*)(C + (size_t)r * N + col) = o;
            }
        }
    }
}

// ---------------------------------------------------------------------------
// Flash-attention with tf32 mma.sync for S=QK^T and O=PV.
// CTA: 128 queries x (b,h). 8 warps, each owns 16 query rows. 64-key tiles.
//   Qs/Ks: stride 132, per-32-chunk permutation slot=(k%4)*8+k/4, XOR ^(8*c32).
//   Vt:    V transposed [d][key], stride 72, key-perm pos=(k%4)*2+k/4,
//          row-XOR ^((d>>2)<<1)  (conflict-free stores AND float2 frag loads).
//   Ps:    P [q][key], stride 72, same key permutation (warp-private rows).
// ---------------------------------------------------------------------------
#define QSTR 132
#define VSTR 72
#define ATTN_SMEM ((128*QSTR + 64*QSTR + 128*VSTR + 128*VSTR) * 4)

__global__ __launch_bounds__(256, 1)
void attn_mma()
{
    extern __shared__ float sm[];
    float* Qs = sm;                    // 128 x 132
    float* Ks = Qs + 128 * QSTR;       // 64 x 132
    float* Vt = Ks + 64 * QSTR;        // 128 x 72
    float* Ps = Vt + 128 * VSTR;       // 128 x 72

    const int tid  = threadIdx.x;
    const int lane = tid & 31;
    const int wid  = tid >> 5;         // 0..7, owns q rows [16*wid, 16*wid+16)
    const int gp   = lane >> 2;
    const int cc   = lane & 3;
    const int qt   = (int)gridDim.x - 1 - (int)blockIdx.x;
    const int bh   = blockIdx.y;
    const int b    = bh >> 4;
    const int h    = bh & 15;
    const float scale = 0.08838834764831845f;   // 1/sqrt(128)
    const size_t rowbase = (size_t)b * SEQ;

    // P-write positions (key permutation within 8-block) for this thread's cols
    const int pos0 = ((2 * cc) & 3) * 2 + ((2 * cc) >> 2);
    const int pos1 = ((2 * cc + 1) & 3) * 2 + ((2 * cc + 1) >> 2);

    // ---- load Q (128 x 128): scale + tf32 round + permuted/XOR store ----
    #pragma unroll
    for (int t = 0; t < 16; t++) {
        int idx = tid + 256 * t;
        int row = idx >> 5;
        int c4  = idx & 31;
        const float* src = g_qkv + (rowbase + qt * 128 + row) * QKVN + h * HDIM + 4 * c4;
        float4 v = *(const float4*)src;
        float vv[4] = {v.x, v.y, v.z, v.w};
        int c32 = c4 >> 3, c4p = c4 & 7;
        float* dst = Qs + row * QSTR + 32 * c32;
        #pragma unroll
        for (int i = 0; i < 4; i++)
            dst[(8 * i + c4p) ^ (8 * c32)] = tf32r(vv[i] * scale);
    }

    float m[2] = {-1e30f, -1e30f}, l[2] = {0.f, 0.f};
    float oacc[16][4];
    #pragma unroll
    for (int nd = 0; nd < 16; nd++)
        #pragma unroll
        for (int q = 0; q < 4; q++) oacc[nd][q] = 0.f;

    const int nkt = 2 * qt + 2;
    for (int kt = 0; kt < nkt; kt++) {
        __syncthreads();   // all warps finished PV reads of previous K/V
        // ---- load K (64x128, permuted) and V (transposed into Vt) ----
        #pragma unroll
        for (int t = 0; t < 8; t++) {
            int idx = tid + 256 * t;
            int row = idx >> 5;          // key within tile
            int c4  = idx & 31;
            const float* src = g_qkv + (rowbase + kt * 64 + row) * QKVN + h * HDIM + 4 * c4;
            float4 kv = *(const float4*)(src + EMBED);
            float4 vv = *(const float4*)(src + 2 * EMBED);
            int c32 = c4 >> 3, c4p = c4 & 7;
            float* kd = Ks + row * QSTR + 32 * c32;
            float kk[4] = {kv.x, kv.y, kv.z, kv.w};
            #pragma unroll
            for (int i = 0; i < 4; i++)
                kd[(8 * i + c4p) ^ (8 * c32)] = tf32r(kk[i]);
            int okey = 8 * (row >> 3) + ((row & 3) << 1) + ((row & 7) >> 2);
            float vvv[4] = {vv.x, vv.y, vv.z, vv.w};
            #pragma unroll
            for (int i = 0; i < 4; i++) {
                int d = 4 * c4 + i;
                Vt[d * VSTR + (okey ^ (((d >> 2) & 31) << 1))] = tf32r(vvv[i]);
            }
        }
        __syncthreads();

        // ---- S = Q K^T (warp tile 16q x 64k) ----
        float sacc[8][4];
        #pragma unroll
        for (int nn = 0; nn < 8; nn++)
            #pragma unroll
            for (int q = 0; q < 4; q++) sacc[nn][q] = 0.f;

        const int qr0 = wid * 16 + gp;
        #pragma unroll
        for (int c32 = 0; c32 < 4; c32++) {
            #pragma unroll
            for (int hh = 0; hh < 2; hh++) {
                int off = 32 * c32 + ((8 * cc + 4 * hh) ^ (8 * c32));
                float4 aq0 = *(const float4*)(Qs + qr0 * QSTR + off);
                float4 aq1 = *(const float4*)(Qs + (qr0 + 8) * QSTR + off);
                #pragma unroll
                for (int nn = 0; nn < 8; nn++) {
                    float4 bk = *(const float4*)(Ks + (8 * nn + gp) * QSTR + off);
                    mma_tf32(sacc[nn], FU(aq0.x), FU(aq1.x), FU(aq0.y), FU(aq1.y),
                             FU(bk.x), FU(bk.y));
                    mma_tf32(sacc[nn], FU(aq0.z), FU(aq1.z), FU(aq0.w), FU(aq1.w),
                             FU(bk.z), FU(bk.w));
                }
            }
        }

        // ---- causal mask (straddling tiles only) ----
        if (kt >= 2 * qt) {
            #pragma unroll
            for (int half = 0; half < 2; half++) {
                int qg = qt * 128 + wid * 16 + gp + 8 * half;
                #pragma unroll
                for (int nn = 0; nn < 8; nn++) {
                    int k0 = kt * 64 + 8 * nn + 2 * cc;
                    if (k0 > qg)     sacc[nn][2 * half]     = -1e30f;
                    if (k0 + 1 > qg) sacc[nn][2 * half + 1] = -1e30f;
                }
            }
        }

        // ---- online softmax (rows gp, gp+8 of warp tile) ----
        #pragma unroll
        for (int half = 0; half < 2; half++) {
            float mx = -1e30f;
            #pragma unroll
            for (int nn = 0; nn < 8; nn++)
                mx = fmaxf(mx, fmaxf(sacc[nn][2 * half], sacc[nn][2 * half + 1]));
            mx = fmaxf(mx, __shfl_xor_sync(0xffffffffu, mx, 1));
            mx = fmaxf(mx, __shfl_xor_sync(0xffffffffu, mx, 2));
            float mnew = fmaxf(m[half], mx);
            float corr = __expf(m[half] - mnew);
            m[half] = mnew;
            float rs = 0.f;
            int prow = wid * 16 + gp + 8 * half;
            #pragma unroll
            for (int nn = 0; nn < 8; nn++) {
                float p0 = __expf(sacc[nn][2 * half] - mnew);
                float p1 = __expf(sacc[nn][2 * half + 1] - mnew);
                rs += p0 + p1;
                Ps[prow * VSTR + 8 * nn + pos0] = tf32r(p0);
                Ps[prow * VSTR + 8 * nn + pos1] = tf32r(p1);
            }
            rs += __shfl_xor_sync(0xffffffffu, rs, 1);
            rs += __shfl_xor_sync(0xffffffffu, rs, 2);
            l[half] = l[half] * corr + rs;
            #pragma unroll
            for (int nd = 0; nd < 16; nd++) {
                oacc[nd][2 * half]     *= corr;
                oacc[nd][2 * half + 1] *= corr;
            }
        }
        __syncwarp();   // P rows are warp-private; make writes visible in-warp

        // ---- O += P V  (warp tile 16q x 128d, K=64 keys) ----
        #pragma unroll
        for (int j = 0; j < 8; j++) {
            float2 ap0 = *(const float2*)(Ps + (wid * 16 + gp) * VSTR + 8 * j + 2 * cc);
            float2 ap1 = *(const float2*)(Ps + (wid * 16 + gp + 8) * VSTR + 8 * j + 2 * cc);
            uint32_t a0 = FU(ap0.x), a1 = FU(ap1.x), a2 = FU(ap0.y), a3 = FU(ap1.y);
            #pragma unroll
            for (int nd = 0; nd < 16; nd++) {
                int d0 = 8 * nd + gp;
                float2 bv = *(const float2*)(Vt + d0 * VSTR +
                                             ((8 * j + 2 * cc) ^ (((d0 >> 2) & 31) << 1)));
                mma_tf32(oacc[nd], a0, a1, a2, a3, FU(bv.x), FU(bv.y));
            }
        }
        __syncwarp();   // PV reads done before next iter's P writes
    }

    // ---- normalize + store ----
    #pragma unroll
    for (int half = 0; half < 2; half++) {
        float inv = 1.0f / l[half];
        size_t row = rowbase + qt * 128 + wid * 16 + gp + 8 * half;
        #pragma unroll
        for (int nd = 0; nd < 16; nd++) {
            float2 o;
            o.x = oacc[nd][2 * half]     * inv;
            o.y = oacc[nd][2 * half + 1] * inv;
            *(float2*)(g_attn + row * EMBED + h * HDIM + 8 * nd + 2 * cc) = o;
        }
    }
}

// ---------------------------------------------------------------------------
extern "C" void kernel_launch(void* const* d_in, const int* in_sizes, int n_in,
                              void* d_out, int out_size)
{
    const float* x    = (const float*)d_in[0];
    const float* Wqkv = (const float*)d_in[1];
    const float* bqkv = (const float*)d_in[2];
    const float* Wout = (const float*)d_in[3];
    const float* bout = (const float*)d_in[4];
    float* out = (float*)d_out;

    float* qkvp = nullptr;
    float* attp = nullptr;
    float* btp  = nullptr;
    cudaGetSymbolAddress((void**)&qkvp, g_qkv);
    cudaGetSymbolAddress((void**)&attp, g_attn);
    cudaGetSymbolAddress((void**)&btp,  g_Bt);

    cudaFuncSetAttribute(attn_mma,
                         cudaFuncAttributeMaxDynamicSharedMemorySize, ATTN_SMEM);
    cudaFuncSetAttribute(gemm_mma,
                         cudaFuncAttributeMaxDynamicSharedMemorySize, GEMM_SMEM);

    transpose_tf32<<<dim3(QKVN / 32, EMBED / 32), dim3(32, 8)>>>(Wqkv, btp, EMBED, QKVN);
    gemm_mma<<<dim3(QKVN / 128, MROWS / 128), 256, GEMM_SMEM>>>(
        x, btp, bqkv, qkvp, MROWS, QKVN, EMBED);
    attn_mma<<<dim3(SEQ / 128, BATCH * NHEADS), 256, ATTN_SMEM>>>();
    transpose_tf32<<<dim3(EMBED / 32, EMBED / 32), dim3(32, 8)>>>(Wout, btp, EMBED, EMBED);
    gemm_mma<<<dim3(EMBED / 128, MROWS / 128), 256, GEMM_SMEM>>>(
        attp, btp, bout, out, MROWS, EMBED, EMBED);
}

// round 5
// speedup vs baseline: 2.2297x; 1.0251x over previous
#include <cuda_runtime.h>
#include <cstdint>

#define EMBED   2048
#define NHEADS  16
#define HDIM    128
#define SEQ     2048
#define BATCH   2
#define QKVN    (3*EMBED)      /* 6144 */
#define MROWS   (BATCH*SEQ)    /* 4096 */

// Scratch (static device globals — allocation-free).
__device__ float g_qkv[(size_t)MROWS * QKVN];    // QKV projection output (fp32)
__device__ float g_attn[(size_t)MROWS * EMBED];  // attention output (fp32)
__device__ float g_Bt[(size_t)QKVN * EMBED];     // transposed tf32 weights [N,K]

__device__ __forceinline__ float tf32r(float x) {
    uint32_t o;
    asm("cvt.rna.tf32.f32 %0, %1;" : "=r"(o) : "f"(x));
    return __uint_as_float(o);
}
__device__ __forceinline__ void mma_tf32(float* c,
                                         uint32_t a0, uint32_t a1, uint32_t a2, uint32_t a3,
                                         uint32_t b0, uint32_t b1) {
    asm volatile(
        "mma.sync.aligned.m16n8k8.row.col.f32.tf32.tf32.f32 "
        "{%0,%1,%2,%3}, {%4,%5,%6,%7}, {%8,%9}, {%0,%1,%2,%3};"
        : "+f"(c[0]), "+f"(c[1]), "+f"(c[2]), "+f"(c[3])
        : "r"(a0), "r"(a1), "r"(a2), "r"(a3), "r"(b0), "r"(b1));
}
#define FU(x) __float_as_uint(x)

// ---------------------------------------------------------------------------
// Weight transpose + tf32 round:  W[K,N] fp32  ->  Wt[N,K] tf32-in-fp32
// ---------------------------------------------------------------------------
__global__ void transpose_tf32(const float* __restrict__ W, float* __restrict__ Wt,
                               int K, int N)
{
    __shared__ float t[32][33];
    const int kb = blockIdx.y * 32, nb = blockIdx.x * 32;
    const int x = threadIdx.x, y = threadIdx.y;  // (32, 8)
    #pragma unroll
    for (int i = 0; i < 32; i += 8)
        t[y + i][x] = W[(size_t)(kb + y + i) * N + nb + x];
    __syncthreads();
    #pragma unroll
    for (int i = 0; i < 32; i += 8)
        Wt[(size_t)(nb + y + i) * K + kb + x] = tf32r(t[x][y + i]);
}

// ---------------------------------------------------------------------------
// TF32 mma.sync GEMM + bias: single __syncthreads per K-stage.
// mma(buf s) reads buffer s while sts fills buffer 1-s (free since stage s-1).
// ---------------------------------------------------------------------------
#define SST 36
#define GEMM_SMEM (4 * 128 * SST * 4)

__global__ __launch_bounds__(256, 1)
void gemm_mma(const float* __restrict__ A, const float* __restrict__ Bt,
              const float* __restrict__ bias, float* __restrict__ C,
              int M, int N, int K)
{
    extern __shared__ float sm[];
    float* AsB = sm;
    float* BsB = sm + 2 * 128 * SST;

    const int tid  = threadIdx.x;
    const int lane = tid & 31;
    const int wid  = tid >> 5;
    const int wm   = wid & 3;
    const int wn   = wid >> 2;
    const int m0   = blockIdx.y * 128;
    const int n0   = blockIdx.x * 128;
    const int gp   = lane >> 2;
    const int cc   = lane & 3;

    float4 pa[4], pb[4];

    auto ldg = [&](int k0) {
        #pragma unroll
        for (int t = 0; t < 4; t++) {
            int idx = tid + 256 * t;
            int row = idx >> 3, c4 = idx & 7;
            pa[t] = *(const float4*)(A  + (size_t)(m0 + row) * K + k0 + 4 * c4);
            pb[t] = *(const float4*)(Bt + (size_t)(n0 + row) * K + k0 + 4 * c4);
        }
    };
    auto sts = [&](int buf) {
        float* a = AsB + buf * 128 * SST;
        float* b = BsB + buf * 128 * SST;
        #pragma unroll
        for (int t = 0; t < 4; t++) {
            int idx = tid + 256 * t;
            int row = idx >> 3, c4 = idx & 7;
            float* ar = a + row * SST;
            float* br = b + row * SST;
            ar[c4]      = tf32r(pa[t].x);
            ar[8 + c4]  = tf32r(pa[t].y);
            ar[16 + c4] = tf32r(pa[t].z);
            ar[24 + c4] = tf32r(pa[t].w);
            br[c4]      = pb[t].x;
            br[8 + c4]  = pb[t].y;
            br[16 + c4] = pb[t].z;
            br[24 + c4] = pb[t].w;
        }
    };

    float acc[2][8][4];
    #pragma unroll
    for (int ma = 0; ma < 2; ma++)
        #pragma unroll
        for (int nn = 0; nn < 8; nn++)
            #pragma unroll
            for (int q = 0; q < 4; q++) acc[ma][nn][q] = 0.f;

    ldg(0); sts(0); __syncthreads();

    const int NST = K >> 5;
    for (int s = 0; s < NST; s++) {
        const int buf = s & 1;
        if (s + 1 < NST) ldg((s + 1) << 5);

        const float* a = AsB + buf * 128 * SST;
        const float* b = BsB + buf * 128 * SST;

        #pragma unroll
        for (int h = 0; h < 2; h++) {
            float4 av[4], bv[8];
            #pragma unroll
            for (int r = 0; r < 4; r++)
                av[r] = *(const float4*)(a + (wm * 32 + gp + 8 * r) * SST + 8 * cc + 4 * h);
            #pragma unroll
            for (int nn = 0; nn < 8; nn++)
                bv[nn] = *(const float4*)(b + (wn * 64 + gp + 8 * nn) * SST + 8 * cc + 4 * h);

            #pragma unroll
            for (int ma = 0; ma < 2; ma++) {
                uint32_t a0 = FU(av[2 * ma].x), a1 = FU(av[2 * ma + 1].x);
                uint32_t a2 = FU(av[2 * ma].y), a3 = FU(av[2 * ma + 1].y);
                #pragma unroll
                for (int nn = 0; nn < 8; nn++)
                    mma_tf32(acc[ma][nn], a0, a1, a2, a3, FU(bv[nn].x), FU(bv[nn].y));
                uint32_t a4 = FU(av[2 * ma].z), a5 = FU(av[2 * ma + 1].z);
                uint32_t a6 = FU(av[2 * ma].w), a7 = FU(av[2 * ma + 1].w);
                #pragma unroll
                for (int nn = 0; nn < 8; nn++)
                    mma_tf32(acc[ma][nn], a4, a5, a6, a7, FU(bv[nn].z), FU(bv[nn].w));
            }
        }
        if (s + 1 < NST) sts(1 - buf);   // writes the buffer NOT being read
        __syncthreads();                  // single barrier per stage
    }

    #pragma unroll
    for (int ma = 0; ma < 2; ma++) {
        int rbase = m0 + wm * 32 + ma * 16 + gp;
        #pragma unroll
        for (int half = 0; half < 2; half++) {
            int r = rbase + 8 * half;
            #pragma unroll
            for (int nn = 0; nn < 8; nn++) {
                int col = n0 + wn * 64 + 8 * nn + 2 * cc;
                float2 bb = *(const float2*)(bias + col);
                float2 o;
                o.x = acc[ma][nn][2 * half + 0] + bb.x;
                o.y = acc[ma][nn][2 * half + 1] + bb.y;
                *(float2*)(C + (size_t)r * N + col) = o;
            }
        }
    }
}

// ---------------------------------------------------------------------------
// Flash-attention (tf32 mma.sync) with K/V register prefetch:
// gmem loads for tile kt+1 are issued before the compute of tile kt, hiding
// the ~600-cycle load latency behind S/softmax/PV.
// ---------------------------------------------------------------------------
#define QSTR 132
#define VSTR 72
#define ATTN_SMEM ((128*QSTR + 64*QSTR + 128*VSTR + 128*VSTR) * 4)

__global__ __launch_bounds__(256, 1)
void attn_mma()
{
    extern __shared__ float sm[];
    float* Qs = sm;                    // 128 x 132
    float* Ks = Qs + 128 * QSTR;       // 64 x 132
    float* Vt = Ks + 64 * QSTR;        // 128 x 72 (V transposed)
    float* Ps = Vt + 128 * VSTR;       // 128 x 72

    const int tid  = threadIdx.x;
    const int lane = tid & 31;
    const int wid  = tid >> 5;
    const int gp   = lane >> 2;
    const int cc   = lane & 3;
    const int qt   = (int)gridDim.x - 1 - (int)blockIdx.x;
    const int bh   = blockIdx.y;
    const int b    = bh >> 4;
    const int h    = bh & 15;
    const float scale = 0.08838834764831845f;   // 1/sqrt(128)
    const size_t rowbase = (size_t)b * SEQ;

    const int pos0 = ((2 * cc) & 3) * 2 + ((2 * cc) >> 2);
    const int pos1 = ((2 * cc + 1) & 3) * 2 + ((2 * cc + 1) >> 2);

    // ---- load Q (128 x 128): scale + tf32 round + permuted/XOR store ----
    #pragma unroll
    for (int t = 0; t < 16; t++) {
        int idx = tid + 256 * t;
        int row = idx >> 5;
        int c4  = idx & 31;
        const float* src = g_qkv + (rowbase + qt * 128 + row) * QKVN + h * HDIM + 4 * c4;
        float4 v = *(const float4*)src;
        float vv[4] = {v.x, v.y, v.z, v.w};
        int c32 = c4 >> 3, c4p = c4 & 7;
        float* dst = Qs + row * QSTR + 32 * c32;
        #pragma unroll
        for (int i = 0; i < 4; i++)
            dst[(8 * i + c4p) ^ (8 * c32)] = tf32r(vv[i] * scale);
    }

    // ---- K/V register staging ----
    float4 kvK[8], kvV[8];
    auto ldgKV = [&](int kt) {
        #pragma unroll
        for (int t = 0; t < 8; t++) {
            int idx = tid + 256 * t;
            int row = idx >> 5;
            int c4  = idx & 31;
            const float* src = g_qkv + (rowbase + kt * 64 + row) * QKVN + h * HDIM + 4 * c4;
            kvK[t] = *(const float4*)(src + EMBED);
            kvV[t] = *(const float4*)(src + 2 * EMBED);
        }
    };
    auto stsKV = [&]() {
        #pragma unroll
        for (int t = 0; t < 8; t++) {
            int idx = tid + 256 * t;
            int row = idx >> 5;
            int c4  = idx & 31;
            int c32 = c4 >> 3, c4p = c4 & 7;
            float* kd = Ks + row * QSTR + 32 * c32;
            float kk[4] = {kvK[t].x, kvK[t].y, kvK[t].z, kvK[t].w};
            #pragma unroll
            for (int i = 0; i < 4; i++)
                kd[(8 * i + c4p) ^ (8 * c32)] = tf32r(kk[i]);
            int okey = 8 * (row >> 3) + ((row & 3) << 1) + ((row & 7) >> 2);
            float vvv[4] = {kvV[t].x, kvV[t].y, kvV[t].z, kvV[t].w};
            #pragma unroll
            for (int i = 0; i < 4; i++) {
                int d = 4 * c4 + i;
                Vt[d * VSTR + (okey ^ (((d >> 2) & 31) << 1))] = tf32r(vvv[i]);
            }
        }
    };

    float m[2] = {-1e30f, -1e30f}, l[2] = {0.f, 0.f};
    float oacc[16][4];
    #pragma unroll
    for (int nd = 0; nd < 16; nd++)
        #pragma unroll
        for (int q = 0; q < 4; q++) oacc[nd][q] = 0.f;

    const int nkt = 2 * qt + 2;
    ldgKV(0);
    for (int kt = 0; kt < nkt; kt++) {
        __syncthreads();   // prev PV reads done (also fences Q stores on kt==0)
        stsKV();
        __syncthreads();
        if (kt + 1 < nkt) ldgKV(kt + 1);   // in flight during compute below

        // ---- S = Q K^T (warp tile 16q x 64k) ----
        float sacc[8][4];
        #pragma unroll
        for (int nn = 0; nn < 8; nn++)
            #pragma unroll
            for (int q = 0; q < 4; q++) sacc[nn][q] = 0.f;

        const int qr0 = wid * 16 + gp;
        #pragma unroll
        for (int c32 = 0; c32 < 4; c32++) {
            #pragma unroll
            for (int hh = 0; hh < 2; hh++) {
                int off = 32 * c32 + ((8 * cc + 4 * hh) ^ (8 * c32));
                float4 aq0 = *(const float4*)(Qs + qr0 * QSTR + off);
                float4 aq1 = *(const float4*)(Qs + (qr0 + 8) * QSTR + off);
                #pragma unroll
                for (int nn = 0; nn < 8; nn++) {
                    float4 bk = *(const float4*)(Ks + (8 * nn + gp) * QSTR + off);
                    mma_tf32(sacc[nn], FU(aq0.x), FU(aq1.x), FU(aq0.y), FU(aq1.y),
                             FU(bk.x), FU(bk.y));
                    mma_tf32(sacc[nn], FU(aq0.z), FU(aq1.z), FU(aq0.w), FU(aq1.w),
                             FU(bk.z), FU(bk.w));
                }
            }
        }

        // ---- causal mask (straddling tiles only) ----
        if (kt >= 2 * qt) {
            #pragma unroll
            for (int half = 0; half < 2; half++) {
                int qg = qt * 128 + wid * 16 + gp + 8 * half;
                #pragma unroll
                for (int nn = 0; nn < 8; nn++) {
                    int k0 = kt * 64 + 8 * nn + 2 * cc;
                    if (k0 > qg)     sacc[nn][2 * half]     = -1e30f;
                    if (k0 + 1 > qg) sacc[nn][2 * half + 1] = -1e30f;
                }
            }
        }

        // ---- online softmax ----
        #pragma unroll
        for (int half = 0; half < 2; half++) {
            float mx = -1e30f;
            #pragma unroll
            for (int nn = 0; nn < 8; nn++)
                mx = fmaxf(mx, fmaxf(sacc[nn][2 * half], sacc[nn][2 * half + 1]));
            mx = fmaxf(mx, __shfl_xor_sync(0xffffffffu, mx, 1));
            mx = fmaxf(mx, __shfl_xor_sync(0xffffffffu, mx, 2));
            float mnew = fmaxf(m[half], mx);
            float corr = __expf(m[half] - mnew);
            m[half] = mnew;
            float rs = 0.f;
            int prow = wid * 16 + gp + 8 * half;
            #pragma unroll
            for (int nn = 0; nn < 8; nn++) {
                float p0 = __expf(sacc[nn][2 * half] - mnew);
                float p1 = __expf(sacc[nn][2 * half + 1] - mnew);
                rs += p0 + p1;
                Ps[prow * VSTR + 8 * nn + pos0] = tf32r(p0);
                Ps[prow * VSTR + 8 * nn + pos1] = tf32r(p1);
            }
            rs += __shfl_xor_sync(0xffffffffu, rs, 1);
            rs += __shfl_xor_sync(0xffffffffu, rs, 2);
            l[half] = l[half] * corr + rs;
            #pragma unroll
            for (int nd = 0; nd < 16; nd++) {
                oacc[nd][2 * half]     *= corr;
                oacc[nd][2 * half + 1] *= corr;
            }
        }
        __syncwarp();

        // ---- O += P V ----
        #pragma unroll
        for (int j = 0; j < 8; j++) {
            float2 ap0 = *(const float2*)(Ps + (wid * 16 + gp) * VSTR + 8 * j + 2 * cc);
            float2 ap1 = *(const float2*)(Ps + (wid * 16 + gp + 8) * VSTR + 8 * j + 2 * cc);
            uint32_t a0 = FU(ap0.x), a1 = FU(ap1.x), a2 = FU(ap0.y), a3 = FU(ap1.y);
            #pragma unroll
            for (int nd = 0; nd < 16; nd++) {
                int d0 = 8 * nd + gp;
                float2 bv = *(const float2*)(Vt + d0 * VSTR +
                                             ((8 * j + 2 * cc) ^ (((d0 >> 2) & 31) << 1)));
                mma_tf32(oacc[nd], a0, a1, a2, a3, FU(bv.x), FU(bv.y));
            }
        }
        __syncwarp();
    }

    // ---- normalize + store ----
    #pragma unroll
    for (int half = 0; half < 2; half++) {
        float inv = 1.0f / l[half];
        size_t row = rowbase + qt * 128 + wid * 16 + gp + 8 * half;
        #pragma unroll
        for (int nd = 0; nd < 16; nd++) {
            float2 o;
            o.x = oacc[nd][2 * half]     * inv;
            o.y = oacc[nd][2 * half + 1] * inv;
            *(float2*)(g_attn + row * EMBED + h * HDIM + 8 * nd + 2 * cc) = o;
        }
    }
}

// ---------------------------------------------------------------------------
extern "C" void kernel_launch(void* const* d_in, const int* in_sizes, int n_in,
                              void* d_out, int out_size)
{
    const float* x    = (const float*)d_in[0];
    const float* Wqkv = (const float*)d_in[1];
    const float* bqkv = (const float*)d_in[2];
    const float* Wout = (const float*)d_in[3];
    const float* bout = (const float*)d_in[4];
    float* out = (float*)d_out;

    float* qkvp = nullptr;
    float* attp = nullptr;
    float* btp  = nullptr;
    cudaGetSymbolAddress((void**)&qkvp, g_qkv);
    cudaGetSymbolAddress((void**)&attp, g_attn);
    cudaGetSymbolAddress((void**)&btp,  g_Bt);

    cudaFuncSetAttribute(attn_mma,
                         cudaFuncAttributeMaxDynamicSharedMemorySize, ATTN_SMEM);
    cudaFuncSetAttribute(gemm_mma,
                         cudaFuncAttributeMaxDynamicSharedMemorySize, GEMM_SMEM);

    transpose_tf32<<<dim3(QKVN / 32, EMBED / 32), dim3(32, 8)>>>(Wqkv, btp, EMBED, QKVN);
    gemm_mma<<<dim3(QKVN / 128, MROWS / 128), 256, GEMM_SMEM>>>(
        x, btp, bqkv, qkvp, MROWS, QKVN, EMBED);
    attn_mma<<<dim3(SEQ / 128, BATCH * NHEADS), 256, ATTN_SMEM>>>();
    transpose_tf32<<<dim3(EMBED / 32, EMBED / 32), dim3(32, 8)>>>(Wout, btp, EMBED, EMBED);
    gemm_mma<<<dim3(EMBED / 128, MROWS / 128), 256, GEMM_SMEM>>>(
        attp, btp, bout, out, MROWS, EMBED, EMBED);
}

// round 6
// speedup vs baseline: 2.5242x; 1.1321x over previous
#include <cuda_runtime.h>
#include <cstdint>

#define EMBED   2048
#define NHEADS  16
#define HDIM    128
#define SEQ     2048
#define BATCH   2
#define QKVN    (3*EMBED)      /* 6144 */
#define MROWS   (BATCH*SEQ)    /* 4096 */

// Scratch (static device globals — allocation-free).
__device__ float g_qkv[(size_t)MROWS * QKVN];    // QKV projection output (fp32)
__device__ float g_attn[(size_t)MROWS * EMBED];  // attention out (permuted tf32)
__device__ float g_Bt[(size_t)QKVN * EMBED];     // weights [N,K] permuted tf32
__device__ float g_xP[(size_t)MROWS * EMBED];    // x permuted tf32

__device__ __forceinline__ float tf32r(float x) {
    uint32_t o;
    asm("cvt.rna.tf32.f32 %0, %1;" : "=r"(o) : "f"(x));
    return __uint_as_float(o);
}
__device__ __forceinline__ void mma_tf32(float* c,
                                         uint32_t a0, uint32_t a1, uint32_t a2, uint32_t a3,
                                         uint32_t b0, uint32_t b1) {
    asm volatile(
        "mma.sync.aligned.m16n8k8.row.col.f32.tf32.tf32.f32 "
        "{%0,%1,%2,%3}, {%4,%5,%6,%7}, {%8,%9}, {%0,%1,%2,%3};"
        : "+f"(c[0]), "+f"(c[1]), "+f"(c[2]), "+f"(c[3])
        : "r"(a0), "r"(a1), "r"(a2), "r"(a3), "r"(b0), "r"(b1));
}
#define FU(x) __float_as_uint(x)

__device__ __forceinline__ uint32_t smem_u32(const void* p) {
    uint32_t a;
    asm("{ .reg .u64 t; cvta.to.shared.u64 t, %1; cvt.u32.u64 %0, t; }"
        : "=r"(a) : "l"(p));
    return a;
}
__device__ __forceinline__ void cp16(uint32_t dst, const void* src) {
    asm volatile("cp.async.ca.shared.global [%0], [%1], 16;"
                 :: "r"(dst), "l"(src) : "memory");
}
#define CP_COMMIT() asm volatile("cp.async.commit_group;" ::: "memory")
#define CP_WAIT2()  asm volatile("cp.async.wait_group 2;"  ::: "memory")

// Permuted layout within each 32-float K-block: value at k (w = k&31) is
// stored at slot (w&3)*8 + (w>>2).  Matches the mma fragment LDS pattern.

// ---------------------------------------------------------------------------
// Permute + tf32-round an [M, 2048] fp32 matrix into fragment layout.
// ---------------------------------------------------------------------------
__global__ void permute_tf32(const float* __restrict__ in, float* __restrict__ out,
                             int total4)
{
    for (int idx = blockIdx.x * blockDim.x + threadIdx.x; idx < total4;
         idx += gridDim.x * blockDim.x) {
        float4 v = *(const float4*)(in + 4 * (size_t)idx);
        int row = idx >> 9;              // 512 float4 per 2048-row
        int c4  = idx & 511;
        float* dst = out + (size_t)row * EMBED + ((c4 >> 3) << 5) + (c4 & 7);
        dst[0]  = tf32r(v.x);
        dst[8]  = tf32r(v.y);
        dst[16] = tf32r(v.z);
        dst[24] = tf32r(v.w);
    }
}

// ---------------------------------------------------------------------------
// Weight transpose + tf32 round + permute:  W[K,N] -> Wt[N,K] (fragment layout)
// ---------------------------------------------------------------------------
__global__ void transpose_tf32(const float* __restrict__ W, float* __restrict__ Wt,
                               int K, int N)
{
    __shared__ float t[32][33];
    const int kb = blockIdx.y * 32, nb = blockIdx.x * 32;
    const int x = threadIdx.x, y = threadIdx.y;  // (32, 8)
    #pragma unroll
    for (int i = 0; i < 32; i += 8)
        t[y + i][x] = W[(size_t)(kb + y + i) * N + nb + x];
    __syncthreads();
    #pragma unroll
    for (int i = 0; i < 32; i += 8)
        Wt[(size_t)(nb + y + i) * K + kb + ((x & 3) << 3) + (x >> 2)] =
            tf32r(t[x][y + i]);
}

// ---------------------------------------------------------------------------
// TF32 mma.sync GEMM + bias, cp.async 4-stage pipeline.
// A and B are pre-permuted + pre-rounded in gmem -> smem fill is a linear
// 16B async copy; fragment loads are the verified conflict-free LDS.128s.
// ---------------------------------------------------------------------------
#define SST 36
#define STAGE_F (2 * 128 * SST)          /* floats per stage (A+B) */
#define NSTAGE 4
#define GEMM_SMEM (NSTAGE * STAGE_F * 4) /* 147456 B */

__global__ __launch_bounds__(256, 1)
void gemm_mma(const float* __restrict__ Ap, const float* __restrict__ Bp,
              const float* __restrict__ bias, float* __restrict__ C,
              int M, int N, int K)
{
    extern __shared__ float sm[];
    const uint32_t smb = smem_u32(sm);

    const int tid  = threadIdx.x;
    const int lane = tid & 31;
    const int wid  = tid >> 5;
    const int wm   = wid & 3;
    const int wn   = wid >> 2;
    const int m0   = blockIdx.y * 128;
    const int n0   = blockIdx.x * 128;
    const int gp   = lane >> 2;
    const int cc   = lane & 3;

    const int frow = tid >> 3;           // fill row (0..127, 2 rows per... 256/8=32? )
    const int fc   = tid & 7;            // fill 16B chunk (0..7)

    auto fill = [&](int s, int st) {
        const int k0 = s << 5;
        uint32_t dA = smb + (uint32_t)(st * STAGE_F) * 4u;
        uint32_t dB = dA + 128 * SST * 4;
        const float* As = Ap + (size_t)m0 * K + k0;
        const float* Bs = Bp + (size_t)n0 * K + k0;
        #pragma unroll
        for (int t = 0; t < 4; t++) {
            int row = frow + 32 * t;
            cp16(dA + (uint32_t)(row * SST + 4 * fc) * 4u, As + (size_t)row * K + 4 * fc);
            cp16(dB + (uint32_t)(row * SST + 4 * fc) * 4u, Bs + (size_t)row * K + 4 * fc);
        }
    };

    float acc[2][8][4];
    #pragma unroll
    for (int ma = 0; ma < 2; ma++)
        #pragma unroll
        for (int nn = 0; nn < 8; nn++)
            #pragma unroll
            for (int q = 0; q < 4; q++) acc[ma][nn][q] = 0.f;

    fill(0, 0); CP_COMMIT();
    fill(1, 1); CP_COMMIT();
    fill(2, 2); CP_COMMIT();

    const int NST = K >> 5;
    for (int s = 0; s < NST; s++) {
        CP_WAIT2();
        __syncthreads();

        const float* a = sm + (s & 3) * STAGE_F;
        const float* b = a + 128 * SST;

        #pragma unroll
        for (int h = 0; h < 2; h++) {
            float4 av[4], bv[8];
            #pragma unroll
            for (int r = 0; r < 4; r++)
                av[r] = *(const float4*)(a + (wm * 32 + gp + 8 * r) * SST + 8 * cc + 4 * h);
            #pragma unroll
            for (int nn = 0; nn < 8; nn++)
                bv[nn] = *(const float4*)(b + (wn * 64 + gp + 8 * nn) * SST + 8 * cc + 4 * h);

            #pragma unroll
            for (int ma = 0; ma < 2; ma++) {
                uint32_t a0 = FU(av[2 * ma].x), a1 = FU(av[2 * ma + 1].x);
                uint32_t a2 = FU(av[2 * ma].y), a3 = FU(av[2 * ma + 1].y);
                #pragma unroll
                for (int nn = 0; nn < 8; nn++)
                    mma_tf32(acc[ma][nn], a0, a1, a2, a3, FU(bv[nn].x), FU(bv[nn].y));
                uint32_t a4 = FU(av[2 * ma].z), a5 = FU(av[2 * ma + 1].z);
                uint32_t a6 = FU(av[2 * ma].w), a7 = FU(av[2 * ma + 1].w);
                #pragma unroll
                for (int nn = 0; nn < 8; nn++)
                    mma_tf32(acc[ma][nn], a4, a5, a6, a7, FU(bv[nn].z), FU(bv[nn].w));
            }
        }
        if (s + 3 < NST) fill(s + 3, (s + 3) & 3);
        CP_COMMIT();
    }

    #pragma unroll
    for (int ma = 0; ma < 2; ma++) {
        int rbase = m0 + wm * 32 + ma * 16 + gp;
        #pragma unroll
        for (int half = 0; half < 2; half++) {
            int r = rbase + 8 * half;
            #pragma unroll
            for (int nn = 0; nn < 8; nn++) {
                int col = n0 + wn * 64 + 8 * nn + 2 * cc;
                float2 bb = *(const float2*)(bias + col);
                float2 o;
                o.x = acc[ma][nn][2 * half + 0] + bb.x;
                o.y = acc[ma][nn][2 * half + 1] + bb.y;
                *(float2*)(C + (size_t)r * N + col) = o;
            }
        }
    }
}

// ---------------------------------------------------------------------------
// Flash-attention (tf32 mma.sync, K/V register prefetch). Epilogue writes the
// output ALREADY permuted + tf32-rounded for the out-projection GEMM.
// ---------------------------------------------------------------------------
#define QSTR 132
#define VSTR 72
#define ATTN_SMEM ((128*QSTR + 64*QSTR + 128*VSTR + 128*VSTR) * 4)

__global__ __launch_bounds__(256, 1)
void attn_mma()
{
    extern __shared__ float sm[];
    float* Qs = sm;                    // 128 x 132
    float* Ks = Qs + 128 * QSTR;       // 64 x 132
    float* Vt = Ks + 64 * QSTR;        // 128 x 72 (V transposed)
    float* Ps = Vt + 128 * VSTR;       // 128 x 72

    const int tid  = threadIdx.x;
    const int lane = tid & 31;
    const int wid  = tid >> 5;
    const int gp   = lane >> 2;
    const int cc   = lane & 3;
    const int qt   = (int)gridDim.x - 1 - (int)blockIdx.x;
    const int bh   = blockIdx.y;
    const int b    = bh >> 4;
    const int h    = bh & 15;
    const float scale = 0.08838834764831845f;   // 1/sqrt(128)
    const size_t rowbase = (size_t)b * SEQ;

    const int pos0 = ((2 * cc) & 3) * 2 + ((2 * cc) >> 2);
    const int pos1 = ((2 * cc + 1) & 3) * 2 + ((2 * cc + 1) >> 2);

    // ---- load Q (128 x 128): scale + tf32 round + permuted/XOR store ----
    #pragma unroll
    for (int t = 0; t < 16; t++) {
        int idx = tid + 256 * t;
        int row = idx >> 5;
        int c4  = idx & 31;
        const float* src = g_qkv + (rowbase + qt * 128 + row) * QKVN + h * HDIM + 4 * c4;
        float4 v = *(const float4*)src;
        float vv[4] = {v.x, v.y, v.z, v.w};
        int c32 = c4 >> 3, c4p = c4 & 7;
        float* dst = Qs + row * QSTR + 32 * c32;
        #pragma unroll
        for (int i = 0; i < 4; i++)
            dst[(8 * i + c4p) ^ (8 * c32)] = tf32r(vv[i] * scale);
    }

    // ---- K/V register staging ----
    float4 kvK[8], kvV[8];
    auto ldgKV = [&](int kt) {
        #pragma unroll
        for (int t = 0; t < 8; t++) {
            int idx = tid + 256 * t;
            int row = idx >> 5;
            int c4  = idx & 31;
            const float* src = g_qkv + (rowbase + kt * 64 + row) * QKVN + h * HDIM + 4 * c4;
            kvK[t] = *(const float4*)(src + EMBED);
            kvV[t] = *(const float4*)(src + 2 * EMBED);
        }
    };
    auto stsKV = [&]() {
        #pragma unroll
        for (int t = 0; t < 8; t++) {
            int idx = tid + 256 * t;
            int row = idx >> 5;
            int c4  = idx & 31;
            int c32 = c4 >> 3, c4p = c4 & 7;
            float* kd = Ks + row * QSTR + 32 * c32;
            float kk[4] = {kvK[t].x, kvK[t].y, kvK[t].z, kvK[t].w};
            #pragma unroll
            for (int i = 0; i < 4; i++)
                kd[(8 * i + c4p) ^ (8 * c32)] = tf32r(kk[i]);
            int okey = 8 * (row >> 3) + ((row & 3) << 1) + ((row & 7) >> 2);
            float vvv[4] = {kvV[t].x, kvV[t].y, kvV[t].z, kvV[t].w};
            #pragma unroll
            for (int i = 0; i < 4; i++) {
                int d = 4 * c4 + i;
                Vt[d * VSTR + (okey ^ (((d >> 2) & 31) << 1))] = tf32r(vvv[i]);
            }
        }
    };

    float m[2] = {-1e30f, -1e30f}, l[2] = {0.f, 0.f};
    float oacc[16][4];
    #pragma unroll
    for (int nd = 0; nd < 16; nd++)
        #pragma unroll
        for (int q = 0; q < 4; q++) oacc[nd][q] = 0.f;

    const int nkt = 2 * qt + 2;
    ldgKV(0);
    for (int kt = 0; kt < nkt; kt++) {
        __syncthreads();
        stsKV();
        __syncthreads();
        if (kt + 1 < nkt) ldgKV(kt + 1);

        // ---- S = Q K^T ----
        float sacc[8][4];
        #pragma unroll
        for (int nn = 0; nn < 8; nn++)
            #pragma unroll
            for (int q = 0; q < 4; q++) sacc[nn][q] = 0.f;

        const int qr0 = wid * 16 + gp;
        #pragma unroll
        for (int c32 = 0; c32 < 4; c32++) {
            #pragma unroll
            for (int hh = 0; hh < 2; hh++) {
                int off = 32 * c32 + ((8 * cc + 4 * hh) ^ (8 * c32));
                float4 aq0 = *(const float4*)(Qs + qr0 * QSTR + off);
                float4 aq1 = *(const float4*)(Qs + (qr0 + 8) * QSTR + off);
                #pragma unroll
                for (int nn = 0; nn < 8; nn++) {
                    float4 bk = *(const float4*)(Ks + (8 * nn + gp) * QSTR + off);
                    mma_tf32(sacc[nn], FU(aq0.x), FU(aq1.x), FU(aq0.y), FU(aq1.y),
                             FU(bk.x), FU(bk.y));
                    mma_tf32(sacc[nn], FU(aq0.z), FU(aq1.z), FU(aq0.w), FU(aq1.w),
                             FU(bk.z), FU(bk.w));
                }
            }
        }

        // ---- causal mask ----
        if (kt >= 2 * qt) {
            #pragma unroll
            for (int half = 0; half < 2; half++) {
                int qg = qt * 128 + wid * 16 + gp + 8 * half;
                #pragma unroll
                for (int nn = 0; nn < 8; nn++) {
                    int k0 = kt * 64 + 8 * nn + 2 * cc;
                    if (k0 > qg)     sacc[nn][2 * half]     = -1e30f;
                    if (k0 + 1 > qg) sacc[nn][2 * half + 1] = -1e30f;
                }
            }
        }

        // ---- online softmax ----
        #pragma unroll
        for (int half = 0; half < 2; half++) {
            float mx = -1e30f;
            #pragma unroll
            for (int nn = 0; nn < 8; nn++)
                mx = fmaxf(mx, fmaxf(sacc[nn][2 * half], sacc[nn][2 * half + 1]));
            mx = fmaxf(mx, __shfl_xor_sync(0xffffffffu, mx, 1));
            mx = fmaxf(mx, __shfl_xor_sync(0xffffffffu, mx, 2));
            float mnew = fmaxf(m[half], mx);
            float corr = __expf(m[half] - mnew);
            m[half] = mnew;
            float rs = 0.f;
            int prow = wid * 16 + gp + 8 * half;
            #pragma unroll
            for (int nn = 0; nn < 8; nn++) {
                float p0 = __expf(sacc[nn][2 * half] - mnew);
                float p1 = __expf(sacc[nn][2 * half + 1] - mnew);
                rs += p0 + p1;
                Ps[prow * VSTR + 8 * nn + pos0] = tf32r(p0);
                Ps[prow * VSTR + 8 * nn + pos1] = tf32r(p1);
            }
            rs += __shfl_xor_sync(0xffffffffu, rs, 1);
            rs += __shfl_xor_sync(0xffffffffu, rs, 2);
            l[half] = l[half] * corr + rs;
            #pragma unroll
            for (int nd = 0; nd < 16; nd++) {
                oacc[nd][2 * half]     *= corr;
                oacc[nd][2 * half + 1] *= corr;
            }
        }
        __syncwarp();

        // ---- O += P V ----
        #pragma unroll
        for (int j = 0; j < 8; j++) {
            float2 ap0 = *(const float2*)(Ps + (wid * 16 + gp) * VSTR + 8 * j + 2 * cc);
            float2 ap1 = *(const float2*)(Ps + (wid * 16 + gp + 8) * VSTR + 8 * j + 2 * cc);
            uint32_t a0 = FU(ap0.x), a1 = FU(ap1.x), a2 = FU(ap0.y), a3 = FU(ap1.y);
            #pragma unroll
            for (int nd = 0; nd < 16; nd++) {
                int d0 = 8 * nd + gp;
                float2 bv = *(const float2*)(Vt + d0 * VSTR +
                                             ((8 * j + 2 * cc) ^ (((d0 >> 2) & 31) << 1)));
                mma_tf32(oacc[nd], a0, a1, a2, a3, FU(bv.x), FU(bv.y));
            }
        }
        __syncwarp();
    }

    // ---- normalize + store (PERMUTED + tf32-rounded for out-proj GEMM) ----
    #pragma unroll
    for (int half = 0; half < 2; half++) {
        float inv = 1.0f / l[half];
        size_t row = rowbase + qt * 128 + wid * 16 + gp + 8 * half;
        float* dst = g_attn + row * EMBED;
        #pragma unroll
        for (int nd = 0; nd < 16; nd++) {
            int j   = 8 * nd + 2 * cc;               // col within head
            int blk = (h * HDIM + j) >> 5;           // 32-block in 2048
            int w   = j & 31;
            int s0  = (w & 3) * 8 + (w >> 2);
            int s1  = ((w + 1) & 3) * 8 + ((w + 1) >> 2);
            dst[blk * 32 + s0] = tf32r(oacc[nd][2 * half]     * inv);
            dst[blk * 32 + s1] = tf32r(oacc[nd][2 * half + 1] * inv);
        }
    }
}

// ---------------------------------------------------------------------------
extern "C" void kernel_launch(void* const* d_in, const int* in_sizes, int n_in,
                              void* d_out, int out_size)
{
    const float* x    = (const float*)d_in[0];
    const float* Wqkv = (const float*)d_in[1];
    const float* bqkv = (const float*)d_in[2];
    const float* Wout = (const float*)d_in[3];
    const float* bout = (const float*)d_in[4];
    float* out = (float*)d_out;

    float* qkvp = nullptr;
    float* attp = nullptr;
    float* btp  = nullptr;
    float* xpp  = nullptr;
    cudaGetSymbolAddress((void**)&qkvp, g_qkv);
    cudaGetSymbolAddress((void**)&attp, g_attn);
    cudaGetSymbolAddress((void**)&btp,  g_Bt);
    cudaGetSymbolAddress((void**)&xpp,  g_xP);

    cudaFuncSetAttribute(attn_mma,
                         cudaFuncAttributeMaxDynamicSharedMemorySize, ATTN_SMEM);
    cudaFuncSetAttribute(gemm_mma,
                         cudaFuncAttributeMaxDynamicSharedMemorySize, GEMM_SMEM);

    // 1) permute + round x -> g_xP   (4096x2048)
    permute_tf32<<<2048, 256>>>(x, xpp, MROWS * EMBED / 4);
    // 2) W_qkv -> [N,K] permuted tf32
    transpose_tf32<<<dim3(QKVN / 32, EMBED / 32), dim3(32, 8)>>>(Wqkv, btp, EMBED, QKVN);
    // 3) QKV projection
    gemm_mma<<<dim3(QKVN / 128, MROWS / 128), 256, GEMM_SMEM>>>(
        xpp, btp, bqkv, qkvp, MROWS, QKVN, EMBED);
    // 4) causal attention (writes permuted output)
    attn_mma<<<dim3(SEQ / 128, BATCH * NHEADS), 256, ATTN_SMEM>>>();
    // 5) W_out -> [N,K] permuted tf32
    transpose_tf32<<<dim3(EMBED / 32, EMBED / 32), dim3(32, 8)>>>(Wout, btp, EMBED, EMBED);
    // 6) output projection
    gemm_mma<<<dim3(EMBED / 128, MROWS / 128), 256, GEMM_SMEM>>>(
        attp, btp, bout, out, MROWS, EMBED, EMBED);
}

// round 8
// speedup vs baseline: 2.5502x; 1.0103x over previous
#include <cuda_runtime.h>
#include <cstdint>

#define EMBED   2048
#define NHEADS  16
#define HDIM    128
#define SEQ     2048
#define BATCH   2
#define QKVN    (3*EMBED)      /* 6144 */
#define MROWS   (BATCH*SEQ)    /* 4096 */

// Scratch (static device globals — allocation-free).
__device__ float g_qP[(size_t)MROWS * EMBED];    // Q: [bh, s, 128] perm+scaled tf32
__device__ float g_kP[(size_t)MROWS * EMBED];    // K: [bh, s, 128] perm tf32
__device__ float g_vT[(size_t)MROWS * EMBED];    // V: [bh, d, 2048] swizzled tf32
__device__ float g_attn[(size_t)MROWS * EMBED];  // attention out (permuted tf32)
__device__ float g_Bt[(size_t)QKVN * EMBED];     // weights [N,K] permuted tf32
__device__ float g_xP[(size_t)MROWS * EMBED];    // x permuted tf32

#define ATT_SCALE 0.08838834764831845f           /* 1/sqrt(128) */

__device__ __forceinline__ float tf32r(float x) {
    uint32_t o;
    asm("cvt.rna.tf32.f32 %0, %1;" : "=r"(o) : "f"(x));
    return __uint_as_float(o);
}
__device__ __forceinline__ void mma_tf32(float* c,
                                         uint32_t a0, uint32_t a1, uint32_t a2, uint32_t a3,
                                         uint32_t b0, uint32_t b1) {
    asm volatile(
        "mma.sync.aligned.m16n8k8.row.col.f32.tf32.tf32.f32 "
        "{%0,%1,%2,%3}, {%4,%5,%6,%7}, {%8,%9}, {%0,%1,%2,%3};"
        : "+f"(c[0]), "+f"(c[1]), "+f"(c[2]), "+f"(c[3])
        : "r"(a0), "r"(a1), "r"(a2), "r"(a3), "r"(b0), "r"(b1));
}
#define FU(x) __float_as_uint(x)

__device__ __forceinline__ uint32_t smem_u32(const void* p) {
    uint32_t a;
    asm("{ .reg .u64 t; cvta.to.shared.u64 t, %1; cvt.u32.u64 %0, t; }"
        : "=r"(a) : "l"(p));
    return a;
}
__device__ __forceinline__ void cp16(uint32_t dst, const void* src) {
    asm volatile("cp.async.ca.shared.global [%0], [%1], 16;"
                 :: "r"(dst), "l"(src) : "memory");
}
#define CP_COMMIT() asm volatile("cp.async.commit_group;" ::: "memory")
#define CP_WAIT0()  asm volatile("cp.async.wait_group 0;"  ::: "memory")
#define CP_WAIT2()  asm volatile("cp.async.wait_group 2;"  ::: "memory")

// Fragment permutation within a 32-float K-block (w = dim & 31):
//   slot = (w&3)*8 + (w>>2), stored at 32*(w>>5) + (slot ^ (8*(w>>5)))
__device__ __forceinline__ int qperm(int w) {
    int c32  = w >> 5;
    int slot = ((w & 3) << 3) + ((w >> 2) & 7);
    return (c32 << 5) + (slot ^ (c32 << 3));
}
// Key permutation within 8-blocks of a 64-key tile (u = key & 63)
__device__ __forceinline__ int okey(int u) {
    return ((u >> 3) << 3) + ((u & 3) << 1) + ((u & 7) >> 2);
}

// ---------------------------------------------------------------------------
// Permute + tf32-round an [M, 2048] fp32 matrix into fragment layout.
// ---------------------------------------------------------------------------
__global__ void permute_tf32(const float* __restrict__ in, float* __restrict__ out,
                             int total4)
{
    for (int idx = blockIdx.x * blockDim.x + threadIdx.x; idx < total4;
         idx += gridDim.x * blockDim.x) {
        float4 v = *(const float4*)(in + 4 * (size_t)idx);
        int row = idx >> 9;
        int c4  = idx & 511;
        float* dst = out + (size_t)row * EMBED + ((c4 >> 3) << 5) + (c4 & 7);
        dst[0]  = tf32r(v.x);
        dst[8]  = tf32r(v.y);
        dst[16] = tf32r(v.z);
        dst[24] = tf32r(v.w);
    }
}

// ---------------------------------------------------------------------------
// Weight transpose + tf32 round + permute:  W[K,N] -> Wt[N,K] (fragment layout)
// ---------------------------------------------------------------------------
__global__ void transpose_tf32(const float* __restrict__ W, float* __restrict__ Wt,
                               int K, int N)
{
    __shared__ float t[32][33];
    const int kb = blockIdx.y * 32, nb = blockIdx.x * 32;
    const int x = threadIdx.x, y = threadIdx.y;  // (32, 8)
    #pragma unroll
    for (int i = 0; i < 32; i += 8)
        t[y + i][x] = W[(size_t)(kb + y + i) * N + nb + x];
    __syncthreads();
    #pragma unroll
    for (int i = 0; i < 32; i += 8)
        Wt[(size_t)(nb + y + i) * K + kb + ((x & 3) << 3) + (x >> 2)] =
            tf32r(t[x][y + i]);
}

// ---------------------------------------------------------------------------
// TF32 mma.sync GEMM, cp.async 4-stage pipeline.
// mode 0: C = A*B^T + bias (fp32 out)
// mode 1: QKV fusion — writes Q (scaled) / K into permuted [bh,s,128] layouts
//         and V transposed+swizzled into [bh,d,2048]; all tf32-rounded.
// ---------------------------------------------------------------------------
#define SST 36
#define STAGE_F (2 * 128 * SST)
#define NSTAGE 4
#define GEMM_SMEM (NSTAGE * STAGE_F * 4)

__global__ __launch_bounds__(256, 1)
void gemm_mma(const float* __restrict__ Ap, const float* __restrict__ Bp,
              const float* __restrict__ bias, float* __restrict__ C,
              int M, int N, int K, int mode)
{
    extern __shared__ float sm[];
    const uint32_t smb = smem_u32(sm);

    const int tid  = threadIdx.x;
    const int lane = tid & 31;
    const int wid  = tid >> 5;
    const int wm   = wid & 3;
    const int wn   = wid >> 2;
    const int m0   = blockIdx.y * 128;
    const int n0   = blockIdx.x * 128;
    const int gp   = lane >> 2;
    const int cc   = lane & 3;

    const int frow = tid >> 3;
    const int fc   = tid & 7;

    auto fill = [&](int s, int st) {
        const int k0 = s << 5;
        uint32_t dA = smb + (uint32_t)(st * STAGE_F) * 4u;
        uint32_t dB = dA + 128 * SST * 4;
        const float* As = Ap + (size_t)m0 * K + k0;
        const float* Bs = Bp + (size_t)n0 * K + k0;
        #pragma unroll
        for (int t = 0; t < 4; t++) {
            int row = frow + 32 * t;
            cp16(dA + (uint32_t)(row * SST + 4 * fc) * 4u, As + (size_t)row * K + 4 * fc);
            cp16(dB + (uint32_t)(row * SST + 4 * fc) * 4u, Bs + (size_t)row * K + 4 * fc);
        }
    };

    float acc[2][8][4];
    #pragma unroll
    for (int ma = 0; ma < 2; ma++)
        #pragma unroll
        for (int nn = 0; nn < 8; nn++)
            #pragma unroll
            for (int q = 0; q < 4; q++) acc[ma][nn][q] = 0.f;

    fill(0, 0); CP_COMMIT();
    fill(1, 1); CP_COMMIT();
    fill(2, 2); CP_COMMIT();

    const int NST = K >> 5;
    for (int s = 0; s < NST; s++) {
        CP_WAIT2();
        __syncthreads();

        const float* a = sm + (s & 3) * STAGE_F;
        const float* b = a + 128 * SST;

        #pragma unroll
        for (int h = 0; h < 2; h++) {
            float4 av[4], bv[8];
            #pragma unroll
            for (int r = 0; r < 4; r++)
                av[r] = *(const float4*)(a + (wm * 32 + gp + 8 * r) * SST + 8 * cc + 4 * h);
            #pragma unroll
            for (int nn = 0; nn < 8; nn++)
                bv[nn] = *(const float4*)(b + (wn * 64 + gp + 8 * nn) * SST + 8 * cc + 4 * h);

            #pragma unroll
            for (int ma = 0; ma < 2; ma++) {
                uint32_t a0 = FU(av[2 * ma].x), a1 = FU(av[2 * ma + 1].x);
                uint32_t a2 = FU(av[2 * ma].y), a3 = FU(av[2 * ma + 1].y);
                #pragma unroll
                for (int nn = 0; nn < 8; nn++)
                    mma_tf32(acc[ma][nn], a0, a1, a2, a3, FU(bv[nn].x), FU(bv[nn].y));
                uint32_t a4 = FU(av[2 * ma].z), a5 = FU(av[2 * ma + 1].z);
                uint32_t a6 = FU(av[2 * ma].w), a7 = FU(av[2 * ma + 1].w);
                #pragma unroll
                for (int nn = 0; nn < 8; nn++)
                    mma_tf32(acc[ma][nn], a4, a5, a6, a7, FU(bv[nn].z), FU(bv[nn].w));
            }
        }
        if (s + 3 < NST) fill(s + 3, (s + 3) & 3);
        CP_COMMIT();
    }

    if (mode == 0) {
        #pragma unroll
        for (int ma = 0; ma < 2; ma++) {
            int rbase = m0 + wm * 32 + ma * 16 + gp;
            #pragma unroll
            for (int half = 0; half < 2; half++) {
                int r = rbase + 8 * half;
                #pragma unroll
                for (int nn = 0; nn < 8; nn++) {
                    int col = n0 + wn * 64 + 8 * nn + 2 * cc;
                    float2 bb = *(const float2*)(bias + col);
                    float2 o;
                    o.x = acc[ma][nn][2 * half + 0] + bb.x;
                    o.y = acc[ma][nn][2 * half + 1] + bb.y;
                    *(float2*)(C + (size_t)r * N + col) = o;
                }
            }
        }
    } else {
        // QKV epilogue: region uniform per CTA (n0 multiple of 128; bounds 2048/4096)
        const int region = n0 >> 11;   // 0=Q, 1=K, 2=V
        #pragma unroll
        for (int ma = 0; ma < 2; ma++) {
            #pragma unroll
            for (int half = 0; half < 2; half++) {
                int r  = m0 + wm * 32 + ma * 16 + gp + 8 * half;
                int bb = r >> 11;       // batch
                int s  = r & 2047;      // token
                #pragma unroll
                for (int nn = 0; nn < 8; nn++) {
                    #pragma unroll
                    for (int j = 0; j < 2; j++) {
                        int col = n0 + wn * 64 + 8 * nn + 2 * cc + j;
                        float v = acc[ma][nn][2 * half + j] + bias[col];
                        int hd = col & 2047;
                        int h  = hd >> 7;
                        int w  = hd & 127;
                        int bh = bb * 16 + h;
                        if (region == 0) {
                            g_qP[((size_t)bh * SEQ + s) * HDIM + qperm(w)] =
                                tf32r(v * ATT_SCALE);
                        } else if (region == 1) {
                            g_kP[((size_t)bh * SEQ + s) * HDIM + qperm(w)] = tf32r(v);
                        } else {
                            int sw = ((w >> 2) & 31) << 1;
                            g_vT[((size_t)bh * HDIM + w) * SEQ +
                                 ((s >> 6) << 6) + (okey(s & 63) ^ sw)] = tf32r(v);
                        }
                    }
                }
            }
        }
    }
}

// ---------------------------------------------------------------------------
// Flash-attention (tf32 mma.sync). Q/K/V are pre-permuted in gmem, so all
// smem fills are linear cp.async. K single-buffered (fill covered by
// softmax+PV), V double-buffered. Output written permuted for out-proj.
// ---------------------------------------------------------------------------
#define QSTR 132
#define VSTR 72
#define ATTN_SMEM ((128*QSTR + 64*QSTR + 2*128*VSTR + 128*VSTR) * 4)

__global__ __launch_bounds__(256, 1)
void attn_mma()
{
    extern __shared__ float sm[];
    float* Qs = sm;                        // 128 x 132
    float* Ks = Qs + 128 * QSTR;           // 64 x 132 (single buffer)
    float* Vb = Ks + 64 * QSTR;            // 2 x (128 x 72)
    float* Ps = Vb + 2 * 128 * VSTR;       // 128 x 72
    const uint32_t smb = smem_u32(sm);
    const uint32_t uQs = smb;
    const uint32_t uKs = smb + 128 * QSTR * 4;
    const uint32_t uVb = uKs + 64 * QSTR * 4;

    const int tid  = threadIdx.x;
    const int lane = tid & 31;
    const int wid  = tid >> 5;
    const int gp   = lane >> 2;
    const int cc   = lane & 3;
    const int qt   = (int)gridDim.x - 1 - (int)blockIdx.x;
    const int bh   = blockIdx.y;
    const size_t qbase = (size_t)bh * SEQ;

    const int pos0 = ((2 * cc) & 3) * 2 + ((2 * cc) >> 2);
    const int pos1 = ((2 * cc + 1) & 3) * 2 + ((2 * cc + 1) >> 2);

    // ---- async fills (all linear copies from pre-permuted gmem) ----
    // Q tile: 128 rows x 32 float4 chunks = 4096 copies
    auto fillQ = [&]() {
        #pragma unroll
        for (int t = 0; t < 16; t++) {
            int idx = tid + 256 * t;
            int row = idx >> 5, ch = idx & 31;
            cp16(uQs + (uint32_t)(row * QSTR + 4 * ch) * 4u,
                 g_qP + (qbase + qt * 128 + row) * HDIM + 4 * ch);
        }
    };
    // K tile: 64 rows x 32 chunks = 2048 copies
    auto fillK = [&](int kt) {
        #pragma unroll
        for (int t = 0; t < 8; t++) {
            int idx = tid + 256 * t;
            int row = idx >> 5, ch = idx & 31;
            cp16(uKs + (uint32_t)(row * QSTR + 4 * ch) * 4u,
                 g_kP + (qbase + kt * 64 + row) * HDIM + 4 * ch);
        }
    };
    // V tile: 128 d-rows x 16 chunks = 2048 copies
    auto fillV = [&](int kt, int buf) {
        uint32_t base = uVb + (uint32_t)(buf * 128 * VSTR) * 4u;
        #pragma unroll
        for (int t = 0; t < 8; t++) {
            int idx = tid + 256 * t;
            int d = idx >> 4, ch = idx & 15;
            cp16(base + (uint32_t)(d * VSTR + 4 * ch) * 4u,
                 g_vT + ((size_t)bh * HDIM + d) * SEQ + kt * 64 + 4 * ch);
        }
    };

    float m[2] = {-1e30f, -1e30f}, l[2] = {0.f, 0.f};
    float oacc[16][4];
    #pragma unroll
    for (int nd = 0; nd < 16; nd++)
        #pragma unroll
        for (int q = 0; q < 4; q++) oacc[nd][q] = 0.f;

    const int nkt = 2 * qt + 2;
    fillQ(); fillK(0); fillV(0, 0);
    CP_COMMIT();

    int vb = 0;
    for (int kt = 0; kt < nkt; kt++) {
        CP_WAIT0();
        __syncthreads();           // all fills visible; prev iter fully done

        if (kt + 1 < nkt) { fillV(kt + 1, 1 - vb); CP_COMMIT(); }

        // ---- S = Q K^T (warp tile 16q x 64k) ----
        float sacc[8][4];
        #pragma unroll
        for (int nn = 0; nn < 8; nn++)
            #pragma unroll
            for (int q = 0; q < 4; q++) sacc[nn][q] = 0.f;

        const int qr0 = wid * 16 + gp;
        #pragma unroll
        for (int c32 = 0; c32 < 4; c32++) {
            #pragma unroll
            for (int hh = 0; hh < 2; hh++) {
                int off = 32 * c32 + ((8 * cc + 4 * hh) ^ (8 * c32));
                float4 aq0 = *(const float4*)(Qs + qr0 * QSTR + off);
                float4 aq1 = *(const float4*)(Qs + (qr0 + 8) * QSTR + off);
                #pragma unroll
                for (int nn = 0; nn < 8; nn++) {
                    float4 bk = *(const float4*)(Ks + (8 * nn + gp) * QSTR + off);
                    mma_tf32(sacc[nn], FU(aq0.x), FU(aq1.x), FU(aq0.y), FU(aq1.y),
                             FU(bk.x), FU(bk.y));
                    mma_tf32(sacc[nn], FU(aq0.z), FU(aq1.z), FU(aq0.w), FU(aq1.w),
                             FU(bk.z), FU(bk.w));
                }
            }
        }
        __syncthreads();           // everyone done reading Ks
        if (kt + 1 < nkt) { fillK(kt + 1); CP_COMMIT(); }

        // ---- causal mask (straddling tiles only) ----
        if (kt >= 2 * qt) {
            #pragma unroll
            for (int half = 0; half < 2; half++) {
                int qg = qt * 128 + wid * 16 + gp + 8 * half;
                #pragma unroll
                for (int nn = 0; nn < 8; nn++) {
                    int k0 = kt * 64 + 8 * nn + 2 * cc;
                    if (k0 > qg)     sacc[nn][2 * half]     = -1e30f;
                    if (k0 + 1 > qg) sacc[nn][2 * half + 1] = -1e30f;
                }
            }
        }

        // ---- online softmax ----
        #pragma unroll
        for (int half = 0; half < 2; half++) {
            float mx = -1e30f;
            #pragma unroll
            for (int nn = 0; nn < 8; nn++)
                mx = fmaxf(mx, fmaxf(sacc[nn][2 * half], sacc[nn][2 * half + 1]));
            mx = fmaxf(mx, __shfl_xor_sync(0xffffffffu, mx, 1));
            mx = fmaxf(mx, __shfl_xor_sync(0xffffffffu, mx, 2));
            float mnew = fmaxf(m[half], mx);
            float corr = __expf(m[half] - mnew);
            m[half] = mnew;
            float rs = 0.f;
            int prow = wid * 16 + gp + 8 * half;
            #pragma unroll
            for (int nn = 0; nn < 8; nn++) {
                float p0 = __expf(sacc[nn][2 * half] - mnew);
                float p1 = __expf(sacc[nn][2 * half + 1] - mnew);
                rs += p0 + p1;
                Ps[prow * VSTR + 8 * nn + pos0] = tf32r(p0);
                Ps[prow * VSTR + 8 * nn + pos1] = tf32r(p1);
            }
            rs += __shfl_xor_sync(0xffffffffu, rs, 1);
            rs += __shfl_xor_sync(0xffffffffu, rs, 2);
            l[half] = l[half] * corr + rs;
            #pragma unroll
            for (int nd = 0; nd < 16; nd++) {
                oacc[nd][2 * half]     *= corr;
                oacc[nd][2 * half + 1] *= corr;
            }
        }
        __syncwarp();

        // ---- O += P V ----
        const float* Vt = Vb + vb * 128 * VSTR;
        #pragma unroll
        for (int j = 0; j < 8; j++) {
            float2 ap0 = *(const float2*)(Ps + (wid * 16 + gp) * VSTR + 8 * j + 2 * cc);
            float2 ap1 = *(const float2*)(Ps + (wid * 16 + gp + 8) * VSTR + 8 * j + 2 * cc);
            uint32_t a0 = FU(ap0.x), a1 = FU(ap1.x), a2 = FU(ap0.y), a3 = FU(ap1.y);
            #pragma unroll
            for (int nd = 0; nd < 16; nd++) {
                int d0 = 8 * nd + gp;
                float2 bv = *(const float2*)(Vt + d0 * VSTR +
                                             ((8 * j + 2 * cc) ^ (((d0 >> 2) & 31) << 1)));
                mma_tf32(oacc[nd], a0, a1, a2, a3, FU(bv.x), FU(bv.y));
            }
        }
        __syncwarp();
        vb ^= 1;
    }

    // ---- normalize + store (permuted + tf32-rounded for out-proj GEMM) ----
    const int b = bh >> 4, h = bh & 15;
    #pragma unroll
    for (int half = 0; half < 2; half++) {
        float inv = 1.0f / l[half];
        size_t row = (size_t)b * SEQ + qt * 128 + wid * 16 + gp + 8 * half;
        float* dst = g_attn + row * EMBED;
        #pragma unroll
        for (int nd = 0; nd < 16; nd++) {
            int j   = 8 * nd + 2 * cc;
            int blk = (h * HDIM + j) >> 5;
            int w   = j & 31;
            int s0  = (w & 3) * 8 + (w >> 2);
            int s1  = ((w + 1) & 3) * 8 + ((w + 1) >> 2);
            dst[blk * 32 + s0] = tf32r(oacc[nd][2 * half]     * inv);
            dst[blk * 32 + s1] = tf32r(oacc[nd][2 * half + 1] * inv);
        }
    }
}

// ---------------------------------------------------------------------------
extern "C" void kernel_launch(void* const* d_in, const int* in_sizes, int n_in,
                              void* d_out, int out_size)
{
    const float* x    = (const float*)d_in[0];
    const float* Wqkv = (const float*)d_in[1];
    const float* bqkv = (const float*)d_in[2];
    const float* Wout = (const float*)d_in[3];
    const float* bout = (const float*)d_in[4];
    float* out = (float*)d_out;

    float* attp = nullptr;
    float* btp  = nullptr;
    float* xpp  = nullptr;
    cudaGetSymbolAddress((void**)&attp, g_attn);
    cudaGetSymbolAddress((void**)&btp,  g_Bt);
    cudaGetSymbolAddress((void**)&xpp,  g_xP);

    cudaFuncSetAttribute(attn_mma,
                         cudaFuncAttributeMaxDynamicSharedMemorySize, ATTN_SMEM);
    cudaFuncSetAttribute(gemm_mma,
                         cudaFuncAttributeMaxDynamicSharedMemorySize, GEMM_SMEM);

    // 1) permute + round x
    permute_tf32<<<2048, 256>>>(x, xpp, MROWS * EMBED / 4);
    // 2) W_qkv -> permuted [N,K]
    transpose_tf32<<<dim3(QKVN / 32, EMBED / 32), dim3(32, 8)>>>(Wqkv, btp, EMBED, QKVN);
    // 3) QKV projection, fused epilogue -> g_qP / g_kP / g_vT
    gemm_mma<<<dim3(QKVN / 128, MROWS / 128), 256, GEMM_SMEM>>>(
        xpp, btp, bqkv, nullptr, MROWS, QKVN, EMBED, 1);
    // 4) causal attention
    attn_mma<<<dim3(SEQ / 128, BATCH * NHEADS), 256, ATTN_SMEM>>>();
    // 5) W_out -> permuted [N,K]
    transpose_tf32<<<dim3(EMBED / 32, EMBED / 32), dim3(32, 8)>>>(Wout, btp, EMBED, EMBED);
    // 6) output projection
    gemm_mma<<<dim3(EMBED / 128, MROWS / 128), 256, GEMM_SMEM>>>(
        attp, btp, bout, out, MROWS, EMBED, EMBED, 0);
}